// round 3
// baseline (speedup 1.0000x reference)
#include <cuda_runtime.h>
#include <math.h>

#define H  1024
#define H3 3072
#define B  64
#define T  256
#define KC 64
#define JT 8

// ---------------- scratch (static __device__: no allocation at runtime) ----
static __device__ float g_GI0[(size_t)T * B * H3];  // precomputed x@W_ih0^T + b_ih0
static __device__ float g_GXF[T * B];               // x_{t+1}·u + c
static __device__ float g_u[H];
static __device__ float g_v[H];
static __device__ float g_c;
static __device__ float g_h0s[B * H];               // layer0 state
static __device__ float g_h1s[B * H];               // layer1 state
static __device__ float g_h0n[B * H];               // layer0 candidate
static __device__ float g_h1n[B * H];               // layer1 candidate
static __device__ float g_gacc[B];                  // gate dot accumulator

__device__ __forceinline__ float sigf(float x) { return 1.0f / (1.0f + expf(-x)); }

// ---------------- init: broadcast h0 into states, zero gate accum ----------
__global__ void init_kernel(const float* __restrict__ h0)
{
    int b = blockIdx.x;
    for (int j = threadIdx.x; j < H; j += blockDim.x) {
        float v = h0[j];
        g_h0s[b * H + j] = v;
        g_h1s[b * H + j] = v;
    }
    if (threadIdx.x == 0) g_gacc[b] = 0.0f;
}

// ---------------- gate folding: u = gW1^T gWF, v = gW2^T gWF, c scalar -----
__global__ void uvc_kernel(const float* __restrict__ gW1, const float* __restrict__ gW2,
                           const float* __restrict__ gWF, const float* __restrict__ gb1,
                           const float* __restrict__ gb2, const float* __restrict__ gbF)
{
    if (blockIdx.x < 2) {
        const float* W  = (blockIdx.x == 0) ? gW1 : gW2;
        float*       dst = (blockIdx.x == 0) ? g_u : g_v;
        for (int k = threadIdx.x; k < H; k += blockDim.x) {
            float s = 0.0f;
            for (int j = 0; j < H; ++j) s += gWF[j] * W[(size_t)j * H + k];
            dst[k] = s;
        }
    } else {
        __shared__ float red[256];
        float s = 0.0f;
        for (int j = threadIdx.x; j < H; j += blockDim.x) s += gWF[j] * (gb1[j] + gb2[j]);
        red[threadIdx.x] = s;
        __syncthreads();
        for (int off = 128; off > 0; off >>= 1) {
            if (threadIdx.x < off) red[threadIdx.x] += red[threadIdx.x + off];
            __syncthreads();
        }
        if (threadIdx.x == 0) g_c = red[0] + gbF[0];
    }
}

// ---------------- gate input precompute: GXF[t][b] = x[b][min(t+1,T-1)]·u + c
__global__ void gxf_kernel(const float* __restrict__ x)
{
    int t = blockIdx.x, b = blockIdx.y;
    int tn = (t + 1 < T) ? (t + 1) : (T - 1);
    const float* xr = x + ((size_t)b * T + tn) * H;
    float s = 0.0f;
    for (int k = threadIdx.x; k < H; k += blockDim.x) s += xr[k] * g_u[k];
    __shared__ float red[128];
    red[threadIdx.x] = s;
    __syncthreads();
    for (int off = 64; off > 0; off >>= 1) {
        if (threadIdx.x < off) red[threadIdx.x] += red[threadIdx.x + off];
        __syncthreads();
    }
    if (threadIdx.x == 0) g_GXF[t * B + b] = red[0] + g_c;
}

// ---------------- big precompute GEMM: GI0[t][b][3H] = x_t @ W_ih0^T + b ---
// grid (T, H/JT), 128 threads. Thread = (bg 0..15, jj 0..7), computes 4 b x 1 j x 3 gates.
__global__ void gi0_kernel(const float* __restrict__ x, const float* __restrict__ Wih0,
                           const float* __restrict__ bih0)
{
    int t  = blockIdx.x;
    int j0 = blockIdx.y * JT;
    int tid = threadIdx.x;
    int bg = tid >> 3, jj = tid & 7, b0 = bg * 4;

    __shared__ float sx[64][KC + 1];
    __shared__ float sw[24][KC + 1];

    float a0[4] = {0, 0, 0, 0}, a1[4] = {0, 0, 0, 0}, a2[4] = {0, 0, 0, 0};

    for (int kc = 0; kc < H / KC; ++kc) {
        int k0 = kc * KC;
        for (int idx = tid; idx < 64 * (KC / 4); idx += 128) {
            int r = idx >> 4, c4 = idx & 15;
            float4 v = *(const float4*)(x + ((size_t)r * T + t) * H + k0 + c4 * 4);
            sx[r][c4 * 4 + 0] = v.x; sx[r][c4 * 4 + 1] = v.y;
            sx[r][c4 * 4 + 2] = v.z; sx[r][c4 * 4 + 3] = v.w;
        }
        for (int idx = tid; idx < 24 * (KC / 4); idx += 128) {
            int wr = idx >> 4, c4 = idx & 15;
            int jl = wr / 3, g = wr - jl * 3;
            float4 v = *(const float4*)(Wih0 + (size_t)(g * H + j0 + jl) * H + k0 + c4 * 4);
            sw[wr][c4 * 4 + 0] = v.x; sw[wr][c4 * 4 + 1] = v.y;
            sw[wr][c4 * 4 + 2] = v.z; sw[wr][c4 * 4 + 3] = v.w;
        }
        __syncthreads();
        #pragma unroll 8
        for (int k = 0; k < KC; ++k) {
            float w0 = sw[jj * 3 + 0][k], w1 = sw[jj * 3 + 1][k], w2 = sw[jj * 3 + 2][k];
            #pragma unroll
            for (int i = 0; i < 4; ++i) {
                float xv = sx[b0 + i][k];
                a0[i] += xv * w0; a1[i] += xv * w1; a2[i] += xv * w2;
            }
        }
        __syncthreads();
    }
    int j = j0 + jj;
    float br = bih0[j], bz = bih0[H + j], bn = bih0[2 * H + j];
    #pragma unroll
    for (int i = 0; i < 4; ++i) {
        int b = b0 + i;
        size_t base = ((size_t)t * B + b) * H3;
        g_GI0[base + j]         = a0[i] + br;
        g_GI0[base + H + j]     = a1[i] + bz;
        g_GI0[base + 2 * H + j] = a2[i] + bn;
    }
}

// ---------------- layer0 step: h0n = GRUcell(GI0[t], h0s; W_hh0) -----------
__global__ void layer0_kernel(int t, const float* __restrict__ Whh0,
                              const float* __restrict__ bhh0)
{
    int j0 = blockIdx.x * JT;
    int tid = threadIdx.x;
    int bg = tid >> 3, jj = tid & 7, b0 = bg * 4;

    __shared__ float sh[64][KC + 1];
    __shared__ float sw[24][KC + 1];

    float a0[4] = {0, 0, 0, 0}, a1[4] = {0, 0, 0, 0}, a2[4] = {0, 0, 0, 0};

    for (int kc = 0; kc < H / KC; ++kc) {
        int k0 = kc * KC;
        for (int idx = tid; idx < 64 * (KC / 4); idx += 128) {
            int r = idx >> 4, c4 = idx & 15;
            float4 v = *(const float4*)(g_h0s + (size_t)r * H + k0 + c4 * 4);
            sh[r][c4 * 4 + 0] = v.x; sh[r][c4 * 4 + 1] = v.y;
            sh[r][c4 * 4 + 2] = v.z; sh[r][c4 * 4 + 3] = v.w;
        }
        for (int idx = tid; idx < 24 * (KC / 4); idx += 128) {
            int wr = idx >> 4, c4 = idx & 15;
            int jl = wr / 3, g = wr - jl * 3;
            float4 v = *(const float4*)(Whh0 + (size_t)(g * H + j0 + jl) * H + k0 + c4 * 4);
            sw[wr][c4 * 4 + 0] = v.x; sw[wr][c4 * 4 + 1] = v.y;
            sw[wr][c4 * 4 + 2] = v.z; sw[wr][c4 * 4 + 3] = v.w;
        }
        __syncthreads();
        #pragma unroll 8
        for (int k = 0; k < KC; ++k) {
            float w0 = sw[jj * 3 + 0][k], w1 = sw[jj * 3 + 1][k], w2 = sw[jj * 3 + 2][k];
            #pragma unroll
            for (int i = 0; i < 4; ++i) {
                float hv = sh[b0 + i][k];
                a0[i] += hv * w0; a1[i] += hv * w1; a2[i] += hv * w2;
            }
        }
        __syncthreads();
    }
    int j = j0 + jj;
    float br = bhh0[j], bz = bhh0[H + j], bn = bhh0[2 * H + j];
    #pragma unroll
    for (int i = 0; i < 4; ++i) {
        int b = b0 + i;
        const float* gi = g_GI0 + ((size_t)t * B + b) * H3;
        float r = sigf(gi[j] + a0[i] + br);
        float z = sigf(gi[H + j] + a1[i] + bz);
        float n = tanhf(gi[2 * H + j] + r * (a2[i] + bn));
        float hp = g_h0s[b * H + j];
        g_h0n[b * H + j] = (1.0f - z) * n + z * hp;
    }
}

// ---------------- layer1 step: h1n = GRUcell(h0n@Wih1+b, h1s; W_hh1) + gate dot
__global__ void layer1_kernel(const float* __restrict__ Wih1, const float* __restrict__ Whh1,
                              const float* __restrict__ bih1, const float* __restrict__ bhh1)
{
    int j0 = blockIdx.x * JT;
    int tid = threadIdx.x;
    int bg = tid >> 3, jj = tid & 7, b0 = bg * 4;

    __shared__ float sx[64][KC + 1];   // layer0 output (this step's input)
    __shared__ float sh[64][KC + 1];   // layer1 previous state
    __shared__ float sw[48][KC + 1];   // 0..23: W_ih1 rows, 24..47: W_hh1 rows

    float ai0[4] = {0, 0, 0, 0}, ai1[4] = {0, 0, 0, 0}, ai2[4] = {0, 0, 0, 0};
    float ah0[4] = {0, 0, 0, 0}, ah1[4] = {0, 0, 0, 0}, ah2[4] = {0, 0, 0, 0};

    for (int kc = 0; kc < H / KC; ++kc) {
        int k0 = kc * KC;
        for (int idx = tid; idx < 64 * (KC / 4); idx += 128) {
            int r = idx >> 4, c4 = idx & 15;
            float4 v = *(const float4*)(g_h0n + (size_t)r * H + k0 + c4 * 4);
            sx[r][c4 * 4 + 0] = v.x; sx[r][c4 * 4 + 1] = v.y;
            sx[r][c4 * 4 + 2] = v.z; sx[r][c4 * 4 + 3] = v.w;
            float4 u = *(const float4*)(g_h1s + (size_t)r * H + k0 + c4 * 4);
            sh[r][c4 * 4 + 0] = u.x; sh[r][c4 * 4 + 1] = u.y;
            sh[r][c4 * 4 + 2] = u.z; sh[r][c4 * 4 + 3] = u.w;
        }
        for (int idx = tid; idx < 48 * (KC / 4); idx += 128) {
            int wr = idx >> 4, c4 = idx & 15;
            int wl = (wr < 24) ? wr : (wr - 24);
            int jl = wl / 3, g = wl - jl * 3;
            const float* src = (wr < 24) ? Wih1 : Whh1;
            float4 v = *(const float4*)(src + (size_t)(g * H + j0 + jl) * H + k0 + c4 * 4);
            sw[wr][c4 * 4 + 0] = v.x; sw[wr][c4 * 4 + 1] = v.y;
            sw[wr][c4 * 4 + 2] = v.z; sw[wr][c4 * 4 + 3] = v.w;
        }
        __syncthreads();
        #pragma unroll 4
        for (int k = 0; k < KC; ++k) {
            float wi0 = sw[jj * 3 + 0][k], wi1 = sw[jj * 3 + 1][k], wi2 = sw[jj * 3 + 2][k];
            float wh0 = sw[24 + jj * 3 + 0][k], wh1 = sw[24 + jj * 3 + 1][k], wh2 = sw[24 + jj * 3 + 2][k];
            #pragma unroll
            for (int i = 0; i < 4; ++i) {
                float xv = sx[b0 + i][k];
                float hv = sh[b0 + i][k];
                ai0[i] += xv * wi0; ai1[i] += xv * wi1; ai2[i] += xv * wi2;
                ah0[i] += hv * wh0; ah1[i] += hv * wh1; ah2[i] += hv * wh2;
            }
        }
        __syncthreads();
    }
    int j = j0 + jj;
    float bir = bih1[j], biz = bih1[H + j], bin = bih1[2 * H + j];
    float bhr = bhh1[j], bhz = bhh1[H + j], bhn = bhh1[2 * H + j];
    float vj = g_v[j];
    float gp[4];
    #pragma unroll
    for (int i = 0; i < 4; ++i) {
        int b = b0 + i;
        float r = sigf(ai0[i] + bir + ah0[i] + bhr);
        float z = sigf(ai1[i] + biz + ah1[i] + bhz);
        float n = tanhf(ai2[i] + bin + r * (ah2[i] + bhn));
        float hp = g_h1s[b * H + j];
        float hn = (1.0f - z) * n + z * hp;
        g_h1n[b * H + j] = hn;
        gp[i] = hn * vj;
    }
    // reduce gate partials across the 8 jj lanes sharing this (bg) group
    #pragma unroll
    for (int s = 1; s < 8; s <<= 1) {
        #pragma unroll
        for (int i = 0; i < 4; ++i) gp[i] += __shfl_down_sync(0xffffffffu, gp[i], s);
    }
    if ((tid & 7) == 0) {
        #pragma unroll
        for (int i = 0; i < 4; ++i) atomicAdd(&g_gacc[b0 + i], gp[i]);
    }
}

// ---------------- gate + state update + output write -----------------------
__global__ void update_kernel(int t, const int* __restrict__ lengths,
                              const float* __restrict__ h0, float* __restrict__ out)
{
    int b = blockIdx.x;
    __shared__ int s_valid, s_reset;
    if (threadIdx.x == 0) {
        float a = g_GXF[t * B + b] + g_gacc[b];
        g_gacc[b] = 0.0f;
        float graw = sigf(a);
        int len = lengths[b];
        float gt = (t == len - 1) ? 1.0f : graw;
        int valid = (t < len);
        out[(size_t)B * T * H + (size_t)b * T + t] = valid ? gt : 0.0f;
        s_valid = valid;
        s_reset = (gt > 0.5f) && valid;
    }
    __syncthreads();
    int valid = s_valid, reset = s_reset;
    float* orow = out + ((size_t)b * T + t) * H;
    for (int j = threadIdx.x; j < H; j += blockDim.x) {
        float h1n = g_h1n[b * H + j];
        orow[j] = valid ? h1n : 0.0f;
        if (valid) {
            float hi = h0[j];
            g_h0s[b * H + j] = reset ? hi : g_h0n[b * H + j];
            g_h1s[b * H + j] = reset ? hi : h1n;
        }
    }
}

// ---------------- host ------------------------------------------------------
extern "C" void kernel_launch(void* const* d_in, const int* in_sizes, int n_in,
                              void* d_out, int out_size)
{
    (void)in_sizes; (void)n_in; (void)out_size;
    const float* x       = (const float*)d_in[0];
    const float* h0      = (const float*)d_in[1];
    const int*   lengths = (const int*)d_in[2];
    const float* W_ih    = (const float*)d_in[3];
    const float* W_hh    = (const float*)d_in[4];
    const float* b_ih    = (const float*)d_in[5];
    const float* b_hh    = (const float*)d_in[6];
    const float* gW1     = (const float*)d_in[7];
    const float* gb1     = (const float*)d_in[8];
    const float* gW2     = (const float*)d_in[9];
    const float* gb2     = (const float*)d_in[10];
    const float* gWF     = (const float*)d_in[11];
    const float* gbF     = (const float*)d_in[12];
    float* out = (float*)d_out;

    const float* Wih0 = W_ih;
    const float* Wih1 = W_ih + (size_t)H3 * H;
    const float* Whh0 = W_hh;
    const float* Whh1 = W_hh + (size_t)H3 * H;
    const float* bih0 = b_ih;
    const float* bih1 = b_ih + H3;
    const float* bhh0 = b_hh;
    const float* bhh1 = b_hh + H3;

    init_kernel<<<B, 256>>>(h0);
    uvc_kernel<<<3, 256>>>(gW1, gW2, gWF, gb1, gb2, gbF);
    gi0_kernel<<<dim3(T, H / JT), 128>>>(x, Wih0, bih0);
    gxf_kernel<<<dim3(T, B), 128>>>(x);

    for (int t = 0; t < T; ++t) {
        layer0_kernel<<<H / JT, 128>>>(t, Whh0, bhh0);
        layer1_kernel<<<H / JT, 128>>>(Wih1, Whh1, bih1, bhh1);
        update_kernel<<<B, 256>>>(t, lengths, h0, out);
    }
}

// round 4
// speedup vs baseline: 1.4779x; 1.4779x over previous
#include <cuda_runtime.h>
#include <math.h>

#define H  1024
#define H3 3072
#define B  64
#define T  256
#define KC 64
#define JT 8

// ---------------- scratch (static __device__: no allocation at runtime) ----
static __device__ float g_GI0[(size_t)T * B * H3];  // precomputed x@W_ih0^T + b_ih0
static __device__ float g_GXF[T * B];               // x_{t+1}·u + c
static __device__ float g_u[H];
static __device__ float g_v[H];
static __device__ float g_c;
static __device__ float g_h0s[B * H];               // layer0 state
static __device__ float g_h1s[B * H];               // layer1 state
static __device__ float g_h0n[B * H];               // layer0 candidate
static __device__ float g_h1n[B * H];               // layer1 candidate
static __device__ float g_gacc[B];                  // gate dot accumulator

__device__ __forceinline__ float sigf(float x) { return 1.0f / (1.0f + expf(-x)); }

// ---------------- init: broadcast h0 into states, zero gate accum ----------
__global__ void init_kernel(const float* __restrict__ h0)
{
    int b = blockIdx.x;
    for (int j = threadIdx.x; j < H; j += blockDim.x) {
        float v = h0[j];
        g_h0s[b * H + j] = v;
        g_h1s[b * H + j] = v;
    }
    if (threadIdx.x == 0) g_gacc[b] = 0.0f;
}

// ---------------- gate folding: u = gW1^T gWF, v = gW2^T gWF, c scalar -----
__global__ void uvc_kernel(const float* __restrict__ gW1, const float* __restrict__ gW2,
                           const float* __restrict__ gWF, const float* __restrict__ gb1,
                           const float* __restrict__ gb2, const float* __restrict__ gbF)
{
    if (blockIdx.x < 2) {
        const float* W  = (blockIdx.x == 0) ? gW1 : gW2;
        float*       dst = (blockIdx.x == 0) ? g_u : g_v;
        for (int k = threadIdx.x; k < H; k += blockDim.x) {
            float s = 0.0f;
            for (int j = 0; j < H; ++j) s += gWF[j] * W[(size_t)j * H + k];
            dst[k] = s;
        }
    } else {
        __shared__ float red[256];
        float s = 0.0f;
        for (int j = threadIdx.x; j < H; j += blockDim.x) s += gWF[j] * (gb1[j] + gb2[j]);
        red[threadIdx.x] = s;
        __syncthreads();
        for (int off = 128; off > 0; off >>= 1) {
            if (threadIdx.x < off) red[threadIdx.x] += red[threadIdx.x + off];
            __syncthreads();
        }
        if (threadIdx.x == 0) g_c = red[0] + gbF[0];
    }
}

// ---------------- gate input precompute: GXF[t][b] = x[b][min(t+1,T-1)]·u + c
__global__ void gxf_kernel(const float* __restrict__ x)
{
    int t = blockIdx.x, b = blockIdx.y;
    int tn = (t + 1 < T) ? (t + 1) : (T - 1);
    const float* xr = x + ((size_t)b * T + tn) * H;
    float s = 0.0f;
    for (int k = threadIdx.x; k < H; k += blockDim.x) s += xr[k] * g_u[k];
    __shared__ float red[128];
    red[threadIdx.x] = s;
    __syncthreads();
    for (int off = 64; off > 0; off >>= 1) {
        if (threadIdx.x < off) red[threadIdx.x] += red[threadIdx.x + off];
        __syncthreads();
    }
    if (threadIdx.x == 0) g_GXF[t * B + b] = red[0] + g_c;
}

// ---------------- big precompute GEMM: GI0[t][b][3H] = x_t @ W_ih0^T + b ---
// grid (T, H/JT), 128 threads. Thread = (bg 0..15, jj 0..7), computes 4 b x 1 j x 3 gates.
__global__ void gi0_kernel(const float* __restrict__ x, const float* __restrict__ Wih0,
                           const float* __restrict__ bih0)
{
    int t  = blockIdx.x;
    int j0 = blockIdx.y * JT;
    int tid = threadIdx.x;
    int bg = tid >> 3, jj = tid & 7, b0 = bg * 4;

    __shared__ float sx[64][KC + 1];
    __shared__ float sw[24][KC + 1];

    float a0[4] = {0, 0, 0, 0}, a1[4] = {0, 0, 0, 0}, a2[4] = {0, 0, 0, 0};

    for (int kc = 0; kc < H / KC; ++kc) {
        int k0 = kc * KC;
        for (int idx = tid; idx < 64 * (KC / 4); idx += 128) {
            int r = idx >> 4, c4 = idx & 15;
            float4 v = *(const float4*)(x + ((size_t)r * T + t) * H + k0 + c4 * 4);
            sx[r][c4 * 4 + 0] = v.x; sx[r][c4 * 4 + 1] = v.y;
            sx[r][c4 * 4 + 2] = v.z; sx[r][c4 * 4 + 3] = v.w;
        }
        for (int idx = tid; idx < 24 * (KC / 4); idx += 128) {
            int wr = idx >> 4, c4 = idx & 15;
            int jl = wr / 3, g = wr - jl * 3;
            float4 v = *(const float4*)(Wih0 + (size_t)(g * H + j0 + jl) * H + k0 + c4 * 4);
            sw[wr][c4 * 4 + 0] = v.x; sw[wr][c4 * 4 + 1] = v.y;
            sw[wr][c4 * 4 + 2] = v.z; sw[wr][c4 * 4 + 3] = v.w;
        }
        __syncthreads();
        #pragma unroll 8
        for (int k = 0; k < KC; ++k) {
            float w0 = sw[jj * 3 + 0][k], w1 = sw[jj * 3 + 1][k], w2 = sw[jj * 3 + 2][k];
            #pragma unroll
            for (int i = 0; i < 4; ++i) {
                float xv = sx[b0 + i][k];
                a0[i] += xv * w0; a1[i] += xv * w1; a2[i] += xv * w2;
            }
        }
        __syncthreads();
    }
    int j = j0 + jj;
    float br = bih0[j], bz = bih0[H + j], bn = bih0[2 * H + j];
    #pragma unroll
    for (int i = 0; i < 4; ++i) {
        int b = b0 + i;
        size_t base = ((size_t)t * B + b) * H3;
        g_GI0[base + j]         = a0[i] + br;
        g_GI0[base + H + j]     = a1[i] + bz;
        g_GI0[base + 2 * H + j] = a2[i] + bn;
    }
}

// ---------------- layer0 step: h0n = GRUcell(GI0[t], h0s; W_hh0) -----------
__global__ void layer0_kernel(int t, const float* __restrict__ Whh0,
                              const float* __restrict__ bhh0)
{
    int j0 = blockIdx.x * JT;
    int tid = threadIdx.x;
    int bg = tid >> 3, jj = tid & 7, b0 = bg * 4;

    __shared__ float sh[64][KC + 1];
    __shared__ float sw[24][KC + 1];

    float a0[4] = {0, 0, 0, 0}, a1[4] = {0, 0, 0, 0}, a2[4] = {0, 0, 0, 0};

    for (int kc = 0; kc < H / KC; ++kc) {
        int k0 = kc * KC;
        for (int idx = tid; idx < 64 * (KC / 4); idx += 128) {
            int r = idx >> 4, c4 = idx & 15;
            float4 v = *(const float4*)(g_h0s + (size_t)r * H + k0 + c4 * 4);
            sh[r][c4 * 4 + 0] = v.x; sh[r][c4 * 4 + 1] = v.y;
            sh[r][c4 * 4 + 2] = v.z; sh[r][c4 * 4 + 3] = v.w;
        }
        for (int idx = tid; idx < 24 * (KC / 4); idx += 128) {
            int wr = idx >> 4, c4 = idx & 15;
            int jl = wr / 3, g = wr - jl * 3;
            float4 v = *(const float4*)(Whh0 + (size_t)(g * H + j0 + jl) * H + k0 + c4 * 4);
            sw[wr][c4 * 4 + 0] = v.x; sw[wr][c4 * 4 + 1] = v.y;
            sw[wr][c4 * 4 + 2] = v.z; sw[wr][c4 * 4 + 3] = v.w;
        }
        __syncthreads();
        #pragma unroll 8
        for (int k = 0; k < KC; ++k) {
            float w0 = sw[jj * 3 + 0][k], w1 = sw[jj * 3 + 1][k], w2 = sw[jj * 3 + 2][k];
            #pragma unroll
            for (int i = 0; i < 4; ++i) {
                float hv = sh[b0 + i][k];
                a0[i] += hv * w0; a1[i] += hv * w1; a2[i] += hv * w2;
            }
        }
        __syncthreads();
    }
    int j = j0 + jj;
    float br = bhh0[j], bz = bhh0[H + j], bn = bhh0[2 * H + j];
    #pragma unroll
    for (int i = 0; i < 4; ++i) {
        int b = b0 + i;
        const float* gi = g_GI0 + ((size_t)t * B + b) * H3;
        float r = sigf(gi[j] + a0[i] + br);
        float z = sigf(gi[H + j] + a1[i] + bz);
        float n = tanhf(gi[2 * H + j] + r * (a2[i] + bn));
        float hp = g_h0s[b * H + j];
        g_h0n[b * H + j] = (1.0f - z) * n + z * hp;
    }
}

// ---------------- layer1 step: h1n = GRUcell(h0n@Wih1+b, h1s; W_hh1) + gate dot
__global__ void layer1_kernel(const float* __restrict__ Wih1, const float* __restrict__ Whh1,
                              const float* __restrict__ bih1, const float* __restrict__ bhh1)
{
    int j0 = blockIdx.x * JT;
    int tid = threadIdx.x;
    int bg = tid >> 3, jj = tid & 7, b0 = bg * 4;

    __shared__ float sx[64][KC + 1];   // layer0 output (this step's input)
    __shared__ float sh[64][KC + 1];   // layer1 previous state
    __shared__ float sw[48][KC + 1];   // 0..23: W_ih1 rows, 24..47: W_hh1 rows

    float ai0[4] = {0, 0, 0, 0}, ai1[4] = {0, 0, 0, 0}, ai2[4] = {0, 0, 0, 0};
    float ah0[4] = {0, 0, 0, 0}, ah1[4] = {0, 0, 0, 0}, ah2[4] = {0, 0, 0, 0};

    for (int kc = 0; kc < H / KC; ++kc) {
        int k0 = kc * KC;
        for (int idx = tid; idx < 64 * (KC / 4); idx += 128) {
            int r = idx >> 4, c4 = idx & 15;
            float4 v = *(const float4*)(g_h0n + (size_t)r * H + k0 + c4 * 4);
            sx[r][c4 * 4 + 0] = v.x; sx[r][c4 * 4 + 1] = v.y;
            sx[r][c4 * 4 + 2] = v.z; sx[r][c4 * 4 + 3] = v.w;
            float4 u = *(const float4*)(g_h1s + (size_t)r * H + k0 + c4 * 4);
            sh[r][c4 * 4 + 0] = u.x; sh[r][c4 * 4 + 1] = u.y;
            sh[r][c4 * 4 + 2] = u.z; sh[r][c4 * 4 + 3] = u.w;
        }
        for (int idx = tid; idx < 48 * (KC / 4); idx += 128) {
            int wr = idx >> 4, c4 = idx & 15;
            int wl = (wr < 24) ? wr : (wr - 24);
            int jl = wl / 3, g = wl - jl * 3;
            const float* src = (wr < 24) ? Wih1 : Whh1;
            float4 v = *(const float4*)(src + (size_t)(g * H + j0 + jl) * H + k0 + c4 * 4);
            sw[wr][c4 * 4 + 0] = v.x; sw[wr][c4 * 4 + 1] = v.y;
            sw[wr][c4 * 4 + 2] = v.z; sw[wr][c4 * 4 + 3] = v.w;
        }
        __syncthreads();
        #pragma unroll 4
        for (int k = 0; k < KC; ++k) {
            float wi0 = sw[jj * 3 + 0][k], wi1 = sw[jj * 3 + 1][k], wi2 = sw[jj * 3 + 2][k];
            float wh0 = sw[24 + jj * 3 + 0][k], wh1 = sw[24 + jj * 3 + 1][k], wh2 = sw[24 + jj * 3 + 2][k];
            #pragma unroll
            for (int i = 0; i < 4; ++i) {
                float xv = sx[b0 + i][k];
                float hv = sh[b0 + i][k];
                ai0[i] += xv * wi0; ai1[i] += xv * wi1; ai2[i] += xv * wi2;
                ah0[i] += hv * wh0; ah1[i] += hv * wh1; ah2[i] += hv * wh2;
            }
        }
        __syncthreads();
    }
    int j = j0 + jj;
    float bir = bih1[j], biz = bih1[H + j], bin = bih1[2 * H + j];
    float bhr = bhh1[j], bhz = bhh1[H + j], bhn = bhh1[2 * H + j];
    float vj = g_v[j];
    float gp[4];
    #pragma unroll
    for (int i = 0; i < 4; ++i) {
        int b = b0 + i;
        float r = sigf(ai0[i] + bir + ah0[i] + bhr);
        float z = sigf(ai1[i] + biz + ah1[i] + bhz);
        float n = tanhf(ai2[i] + bin + r * (ah2[i] + bhn));
        float hp = g_h1s[b * H + j];
        float hn = (1.0f - z) * n + z * hp;
        g_h1n[b * H + j] = hn;
        gp[i] = hn * vj;
    }
    // reduce gate partials across the 8 jj lanes sharing this (bg) group
    #pragma unroll
    for (int s = 1; s < 8; s <<= 1) {
        #pragma unroll
        for (int i = 0; i < 4; ++i) gp[i] += __shfl_down_sync(0xffffffffu, gp[i], s);
    }
    if ((tid & 7) == 0) {
        #pragma unroll
        for (int i = 0; i < 4; ++i) atomicAdd(&g_gacc[b0 + i], gp[i]);
    }
}

// ---------------- gate + state update + output write -----------------------
__global__ void update_kernel(int t, const int* __restrict__ lengths,
                              const float* __restrict__ h0, float* __restrict__ out)
{
    int b = blockIdx.x;
    __shared__ int s_valid, s_reset;
    if (threadIdx.x == 0) {
        float a = g_GXF[t * B + b] + g_gacc[b];
        g_gacc[b] = 0.0f;
        float graw = sigf(a);
        int len = lengths[b];
        float gt = (t == len - 1) ? 1.0f : graw;
        int valid = (t < len);
        out[(size_t)B * T * H + (size_t)b * T + t] = valid ? gt : 0.0f;
        s_valid = valid;
        s_reset = (gt > 0.5f) && valid;
    }
    __syncthreads();
    int valid = s_valid, reset = s_reset;
    float* orow = out + ((size_t)b * T + t) * H;
    for (int j = threadIdx.x; j < H; j += blockDim.x) {
        float h1n = g_h1n[b * H + j];
        orow[j] = valid ? h1n : 0.0f;
        if (valid) {
            float hi = h0[j];
            g_h0s[b * H + j] = reset ? hi : g_h0n[b * H + j];
            g_h1s[b * H + j] = reset ? hi : h1n;
        }
    }
}

// ---------------- host ------------------------------------------------------
extern "C" void kernel_launch(void* const* d_in, const int* in_sizes, int n_in,
                              void* d_out, int out_size)
{
    (void)in_sizes; (void)n_in; (void)out_size;
    const float* x       = (const float*)d_in[0];
    const float* h0      = (const float*)d_in[1];
    const int*   lengths = (const int*)d_in[2];
    const float* W_ih    = (const float*)d_in[3];
    const float* W_hh    = (const float*)d_in[4];
    const float* b_ih    = (const float*)d_in[5];
    const float* b_hh    = (const float*)d_in[6];
    const float* gW1     = (const float*)d_in[7];
    const float* gb1     = (const float*)d_in[8];
    const float* gW2     = (const float*)d_in[9];
    const float* gb2     = (const float*)d_in[10];
    const float* gWF     = (const float*)d_in[11];
    const float* gbF     = (const float*)d_in[12];
    float* out = (float*)d_out;

    const float* Wih0 = W_ih;
    const float* Wih1 = W_ih + (size_t)H3 * H;
    const float* Whh0 = W_hh;
    const float* Whh1 = W_hh + (size_t)H3 * H;
    const float* bih0 = b_ih;
    const float* bih1 = b_ih + H3;
    const float* bhh0 = b_hh;
    const float* bhh1 = b_hh + H3;

    init_kernel<<<B, 256>>>(h0);
    uvc_kernel<<<3, 256>>>(gW1, gW2, gWF, gb1, gb2, gbF);
    gi0_kernel<<<dim3(T, H / JT), 128>>>(x, Wih0, bih0);
    gxf_kernel<<<dim3(T, B), 128>>>(x);

    for (int t = 0; t < T; ++t) {
        layer0_kernel<<<H / JT, 128>>>(t, Whh0, bhh0);
        layer1_kernel<<<H / JT, 128>>>(Wih1, Whh1, bih1, bhh1);
        update_kernel<<<B, 256>>>(t, lengths, h0, out);
    }
}

// round 5
// speedup vs baseline: 3.9343x; 2.6620x over previous
#include <cuda_runtime.h>
#include <cuda_fp16.h>
#include <math.h>

#define H  1024
#define H3 3072
#define B  64
#define T  256
#define LOSC   2048.0f
#define ILOSC  (1.0f/2048.0f)

// ---------------- static scratch (no runtime allocation) -------------------
static __device__ float g_GI0[(size_t)T * B * H3];   // x@Wih0^T + bih0 (fp32)
static __device__ float g_GXF[T * B];
static __device__ float g_u[H];
static __device__ float g_v[H];
static __device__ float g_c;
static __device__ float g_h0s[B * H];                // fp32 states
static __device__ float g_h1s[B * H];
static __device__ float g_h0n[B * H];                // layer0 candidate fp32
static __device__ float g_GA[B * H3];                // gi1 raw (+bih1)
static __device__ float g_GB[B * H3];                // gh1 raw (+bhh1)

// fragment-packed hi/lo buffers: row-major rows, 256 uint4/row.
// uint4 at (row, ks, tc): k0=16ks+2tc -> {hi2(k0,k0+1), hi2(k0+8,k0+9), lo2*2048, lo2*2048}
static __device__ uint4 g_xp[(size_t)B * T * 256];   // x rows, row index b*T+t
static __device__ uint4 g_pW[4][(size_t)H3 * 256];   // 0:Wih0 1:Whh0 2:Wih1 3:Whh1
static __device__ uint4 g_h0p [B * 256];             // layer0 state packed
static __device__ uint4 g_h1p [B * 256];             // layer1 state packed
static __device__ uint4 g_h0np[B * 256];             // layer0 candidate packed

__device__ __forceinline__ float sigf(float x) { return 1.0f / (1.0f + expf(-x)); }

__device__ __forceinline__ unsigned pk2(float a, float b) {
    __half2 h = __floats2half2_rn(a, b);
    return *reinterpret_cast<unsigned*>(&h);
}
__device__ __forceinline__ float rlo(float x) {
    return (x - __half2float(__float2half_rn(x))) * LOSC;
}
__device__ __forceinline__ uint4 pack4(float v0, float v1, float v8, float v9) {
    uint4 p;
    p.x = pk2(v0, v1);           p.y = pk2(v8, v9);
    p.z = pk2(rlo(v0), rlo(v1)); p.w = pk2(rlo(v8), rlo(v9));
    return p;
}

__device__ __forceinline__ void mma_f16(float* c, unsigned a0, unsigned a1,
                                        unsigned a2, unsigned a3,
                                        unsigned b0, unsigned b1) {
    asm volatile(
        "mma.sync.aligned.m16n8k16.row.col.f32.f16.f16.f32 "
        "{%0,%1,%2,%3}, {%4,%5,%6,%7}, {%8,%9}, {%0,%1,%2,%3};\n"
        : "+f"(c[0]), "+f"(c[1]), "+f"(c[2]), "+f"(c[3])
        : "r"(a0), "r"(a1), "r"(a2), "r"(a3), "r"(b0), "r"(b1));
}
// split product: hi*hi -> ch ; hi*lo' + lo'*hi -> cl (recombine ch + cl*2^-11)
__device__ __forceinline__ void mma3s(float* ch, float* cl, const uint4& al,
                                      const uint4& ah, const uint4& wv) {
    mma_f16(ch, al.x, ah.x, al.y, ah.y, wv.x, wv.y);
    mma_f16(cl, al.x, ah.x, al.y, ah.y, wv.z, wv.w);
    mma_f16(cl, al.z, ah.z, al.w, ah.w, wv.x, wv.y);
}

// ---------------- init ------------------------------------------------------
__global__ void init_kernel(const float* __restrict__ h0)
{
    int b = blockIdx.x;
    int ks = threadIdx.x >> 2, tc = threadIdx.x & 3;
    int j = ks * 16 + 2 * tc;
    float2 a = *(const float2*)(h0 + j);
    float2 c = *(const float2*)(h0 + j + 8);
    *(float2*)(g_h0s + b * H + j)     = a;
    *(float2*)(g_h0s + b * H + j + 8) = c;
    *(float2*)(g_h1s + b * H + j)     = a;
    *(float2*)(g_h1s + b * H + j + 8) = c;
    uint4 p = pack4(a.x, a.y, c.x, c.y);
    g_h0p[(b * 64 + ks) * 4 + tc] = p;
    g_h1p[(b * 64 + ks) * 4 + tc] = p;
}

// ---------------- gate folding ---------------------------------------------
__global__ void uvc_kernel(const float* __restrict__ gW1, const float* __restrict__ gW2,
                           const float* __restrict__ gWF, const float* __restrict__ gb1,
                           const float* __restrict__ gb2, const float* __restrict__ gbF)
{
    int bid = blockIdx.x;
    if (bid < 32) {
        int mat = bid >> 4, kc = bid & 15;
        const float* W = mat ? gW2 : gW1;
        float* dst = mat ? g_v : g_u;
        int k = kc * 64 + threadIdx.x;
        float s = 0.0f;
        for (int j = 0; j < H; ++j) s += gWF[j] * W[(size_t)j * H + k];
        dst[k] = s;
    } else {
        __shared__ float red[64];
        float s = 0.0f;
        for (int j = threadIdx.x; j < H; j += 64) s += gWF[j] * (gb1[j] + gb2[j]);
        red[threadIdx.x] = s;
        __syncthreads();
        for (int off = 32; off > 0; off >>= 1) {
            if (threadIdx.x < off) red[threadIdx.x] += red[threadIdx.x + off];
            __syncthreads();
        }
        if (threadIdx.x == 0) g_c = red[0] + gbF[0];
    }
}

// ---------------- gate input precompute ------------------------------------
__global__ void gxf_kernel(const float* __restrict__ x)
{
    int t = blockIdx.x, b = blockIdx.y;
    int tn = (t + 1 < T) ? (t + 1) : (T - 1);
    const float* xr = x + ((size_t)b * T + tn) * H;
    float s = 0.0f;
    for (int k = threadIdx.x; k < H; k += blockDim.x) s += xr[k] * g_u[k];
    __shared__ float red[128];
    red[threadIdx.x] = s;
    __syncthreads();
    for (int off = 64; off > 0; off >>= 1) {
        if (threadIdx.x < off) red[threadIdx.x] += red[threadIdx.x + off];
        __syncthreads();
    }
    if (threadIdx.x == 0) g_GXF[t * B + b] = red[0] + g_c;
}

// ---------------- pack weights ---------------------------------------------
__global__ void packw_kernel(const float* __restrict__ W_ih, const float* __restrict__ W_hh)
{
    int row = blockIdx.x, mat = blockIdx.y;
    int ks = threadIdx.x >> 2, tc = threadIdx.x & 3;
    const float* src = (mat == 0) ? W_ih : (mat == 1) ? W_hh
                     : (mat == 2) ? (W_ih + (size_t)H3 * H) : (W_hh + (size_t)H3 * H);
    int k0 = ks * 16 + 2 * tc;
    const float* r = src + (size_t)row * H;
    float2 a = *(const float2*)(r + k0);
    float2 c = *(const float2*)(r + k0 + 8);
    g_pW[mat][((size_t)row * 64 + ks) * 4 + tc] = pack4(a.x, a.y, c.x, c.y);
}

// ---------------- pack x ----------------------------------------------------
__global__ void packx_kernel(const float* __restrict__ x)
{
    int t = blockIdx.x, b = blockIdx.y;
    int ks = threadIdx.x >> 2, tc = threadIdx.x & 3;
    int k0 = ks * 16 + 2 * tc;
    const float* r = x + ((size_t)b * T + t) * H;
    float2 a = *(const float2*)(r + k0);
    float2 c = *(const float2*)(r + k0 + 8);
    g_xp[((size_t)(b * T + t) * 64 + ks) * 4 + tc] = pack4(a.x, a.y, c.x, c.y);
}

// ---------------- gi0: GI0[t] = x_t @ Wih0^T + bih0 (tensor) ----------------
// grid (64 j-tiles, T), 256 thr. warp w: mt=w&3 (16 rows), jh=w>>2 (8 j's).
__global__ void gi0_kernel(const float* __restrict__ bih0)
{
    int tid = threadIdx.x, w = tid >> 5, lane = tid & 31;
    int mt = w & 3, jh = w >> 2;
    int g = lane >> 2, tc = lane & 3;
    int j0 = blockIdx.x * 16, t = blockIdx.y;
    int b0 = mt * 16 + g;
    int jrow = j0 + jh * 8 + g;

    float h0a[4] = {0,0,0,0}, l0a[4] = {0,0,0,0};
    float h1a[4] = {0,0,0,0}, l1a[4] = {0,0,0,0};
    float h2a[4] = {0,0,0,0}, l2a[4] = {0,0,0,0};
    const uint4* Ap0 = g_xp + ((size_t)b0 * T + t) * 256 + tc;
    const uint4* Ap1 = Ap0 + (size_t)8 * T * 256;
    const uint4* B0 = g_pW[0] + (size_t)jrow * 256 + tc;
    const uint4* B1 = g_pW[0] + (size_t)(H + jrow) * 256 + tc;
    const uint4* B2 = g_pW[0] + (size_t)(2 * H + jrow) * 256 + tc;

    #pragma unroll 4
    for (int ks = 0; ks < 64; ++ks) {
        uint4 al = Ap0[ks * 4], ah = Ap1[ks * 4];
        uint4 w0 = B0[ks * 4], w1 = B1[ks * 4], w2 = B2[ks * 4];
        mma3s(h0a, l0a, al, ah, w0);
        mma3s(h1a, l1a, al, ah, w1);
        mma3s(h2a, l2a, al, ah, w2);
    }
    int jA = j0 + jh * 8 + 2 * tc;
    float2 br = *(const float2*)(bih0 + jA);
    float2 bz = *(const float2*)(bih0 + H + jA);
    float2 bn = *(const float2*)(bih0 + 2 * H + jA);
    #pragma unroll
    for (int rs = 0; rs < 2; ++rs) {
        int row = b0 + 8 * rs;
        float* dst = g_GI0 + ((size_t)t * B + row) * H3;
        float2 o;
        o.x = h0a[2*rs] + l0a[2*rs]*ILOSC + br.x;
        o.y = h0a[2*rs+1] + l0a[2*rs+1]*ILOSC + br.y; *(float2*)(dst + jA) = o;
        o.x = h1a[2*rs] + l1a[2*rs]*ILOSC + bz.x;
        o.y = h1a[2*rs+1] + l1a[2*rs+1]*ILOSC + bz.y; *(float2*)(dst + H + jA) = o;
        o.x = h2a[2*rs] + l2a[2*rs]*ILOSC + bn.x;
        o.y = h2a[2*rs+1] + l2a[2*rs+1]*ILOSC + bn.y; *(float2*)(dst + 2*H + jA) = o;
    }
}

// ---------------- layer0 step: GEMM + fused GRU + repack --------------------
// grid 64 (j-tile 16), 256 thr.
__global__ void l0_kernel(int t, const float* __restrict__ bhh0)
{
    __shared__ float s_hn[64][17];
    int tid = threadIdx.x, w = tid >> 5, lane = tid & 31;
    int mt = w & 3, jh = w >> 2;
    int g = lane >> 2, tc = lane & 3;
    int j0 = blockIdx.x * 16;
    int b0 = mt * 16 + g;
    int jrow = j0 + jh * 8 + g;

    float h0a[4] = {0,0,0,0}, l0a[4] = {0,0,0,0};
    float h1a[4] = {0,0,0,0}, l1a[4] = {0,0,0,0};
    float h2a[4] = {0,0,0,0}, l2a[4] = {0,0,0,0};
    const uint4* Ap0 = g_h0p + (size_t)b0 * 256 + tc;
    const uint4* Ap1 = Ap0 + 8 * 256;
    const uint4* B0 = g_pW[1] + (size_t)jrow * 256 + tc;
    const uint4* B1 = g_pW[1] + (size_t)(H + jrow) * 256 + tc;
    const uint4* B2 = g_pW[1] + (size_t)(2 * H + jrow) * 256 + tc;

    #pragma unroll 4
    for (int ks = 0; ks < 64; ++ks) {
        uint4 al = Ap0[ks * 4], ah = Ap1[ks * 4];
        uint4 w0 = B0[ks * 4], w1 = B1[ks * 4], w2 = B2[ks * 4];
        mma3s(h0a, l0a, al, ah, w0);
        mma3s(h1a, l1a, al, ah, w1);
        mma3s(h2a, l2a, al, ah, w2);
    }
    int jA = j0 + jh * 8 + 2 * tc;
    float2 bhr = *(const float2*)(bhh0 + jA);
    float2 bhz = *(const float2*)(bhh0 + H + jA);
    float2 bhn = *(const float2*)(bhh0 + 2 * H + jA);
    #pragma unroll
    for (int rs = 0; rs < 2; ++rs) {
        int row = b0 + 8 * rs;
        const float* gi = g_GI0 + ((size_t)t * B + row) * H3;
        float2 gr = *(const float2*)(gi + jA);
        float2 gz = *(const float2*)(gi + H + jA);
        float2 gn = *(const float2*)(gi + 2 * H + jA);
        float2 hp = *(const float2*)(g_h0s + row * H + jA);
        float2 o;
        {
            float ar = h0a[2*rs] + l0a[2*rs]*ILOSC;
            float az = h1a[2*rs] + l1a[2*rs]*ILOSC;
            float an = h2a[2*rs] + l2a[2*rs]*ILOSC;
            float r = sigf(gr.x + ar + bhr.x);
            float z = sigf(gz.x + az + bhz.x);
            float n = tanhf(gn.x + r * (an + bhn.x));
            o.x = (1.0f - z) * n + z * hp.x;
        }
        {
            float ar = h0a[2*rs+1] + l0a[2*rs+1]*ILOSC;
            float az = h1a[2*rs+1] + l1a[2*rs+1]*ILOSC;
            float an = h2a[2*rs+1] + l2a[2*rs+1]*ILOSC;
            float r = sigf(gr.y + ar + bhr.y);
            float z = sigf(gz.y + az + bhz.y);
            float n = tanhf(gn.y + r * (an + bhn.y));
            o.y = (1.0f - z) * n + z * hp.y;
        }
        *(float2*)(g_h0n + row * H + jA) = o;
        s_hn[row][jh * 8 + 2 * tc]     = o.x;
        s_hn[row][jh * 8 + 2 * tc + 1] = o.y;
    }
    __syncthreads();
    // repack this 16-j slice (= one ks) of h0n for all 64 rows
    int b = tid >> 2, tcc = tid & 3;
    int ksb = j0 >> 4;
    g_h0np[(b * 64 + ksb) * 4 + tcc] =
        pack4(s_hn[b][2 * tcc], s_hn[b][2 * tcc + 1],
              s_hn[b][2 * tcc + 8], s_hn[b][2 * tcc + 9]);
}

// ---------------- layer1 GEMMs: 128 blocks (which x j-tile) -----------------
__global__ void l1_kernel(const float* __restrict__ bih1, const float* __restrict__ bhh1)
{
    int which = blockIdx.x >> 6;          // 0: ih (h0n), 1: hh (h1s)
    int j0 = (blockIdx.x & 63) * 16;
    int tid = threadIdx.x, w = tid >> 5, lane = tid & 31;
    int mt = w & 3, jh = w >> 2;
    int g = lane >> 2, tc = lane & 3;
    int b0 = mt * 16 + g;
    int jrow = j0 + jh * 8 + g;

    const uint4* A = which ? g_h1p : g_h0np;
    const uint4* W = which ? g_pW[3] : g_pW[2];
    const float* bias = which ? bhh1 : bih1;
    float* dst0 = which ? g_GB : g_GA;

    float h0a[4] = {0,0,0,0}, l0a[4] = {0,0,0,0};
    float h1a[4] = {0,0,0,0}, l1a[4] = {0,0,0,0};
    float h2a[4] = {0,0,0,0}, l2a[4] = {0,0,0,0};
    const uint4* Ap0 = A + (size_t)b0 * 256 + tc;
    const uint4* Ap1 = Ap0 + 8 * 256;
    const uint4* B0 = W + (size_t)jrow * 256 + tc;
    const uint4* B1 = W + (size_t)(H + jrow) * 256 + tc;
    const uint4* B2 = W + (size_t)(2 * H + jrow) * 256 + tc;

    #pragma unroll 4
    for (int ks = 0; ks < 64; ++ks) {
        uint4 al = Ap0[ks * 4], ah = Ap1[ks * 4];
        uint4 w0 = B0[ks * 4], w1 = B1[ks * 4], w2 = B2[ks * 4];
        mma3s(h0a, l0a, al, ah, w0);
        mma3s(h1a, l1a, al, ah, w1);
        mma3s(h2a, l2a, al, ah, w2);
    }
    int jA = j0 + jh * 8 + 2 * tc;
    float2 br = *(const float2*)(bias + jA);
    float2 bz = *(const float2*)(bias + H + jA);
    float2 bn = *(const float2*)(bias + 2 * H + jA);
    #pragma unroll
    for (int rs = 0; rs < 2; ++rs) {
        int row = b0 + 8 * rs;
        float* dst = dst0 + (size_t)row * H3;
        float2 o;
        o.x = h0a[2*rs] + l0a[2*rs]*ILOSC + br.x;
        o.y = h0a[2*rs+1] + l0a[2*rs+1]*ILOSC + br.y; *(float2*)(dst + jA) = o;
        o.x = h1a[2*rs] + l1a[2*rs]*ILOSC + bz.x;
        o.y = h1a[2*rs+1] + l1a[2*rs+1]*ILOSC + bz.y; *(float2*)(dst + H + jA) = o;
        o.x = h2a[2*rs] + l2a[2*rs]*ILOSC + bn.x;
        o.y = h2a[2*rs+1] + l2a[2*rs+1]*ILOSC + bn.y; *(float2*)(dst + 2*H + jA) = o;
    }
}

// ---------------- update: layer1 GRU + gate + states (one block per b) ------
__global__ void update_kernel(int t, const int* __restrict__ lengths,
                              const float* __restrict__ h0, float* __restrict__ out)
{
    int b = blockIdx.x, tid = threadIdx.x;
    int ks = tid >> 2, tc = tid & 3;
    int j0a = ks * 16 + 2 * tc;
    const float* A  = g_GA + (size_t)b * H3;
    const float* Bm = g_GB + (size_t)b * H3;

    float h1n[4];
    float dot = 0.0f;
    #pragma unroll
    for (int s2 = 0; s2 < 2; ++s2) {
        int j = j0a + 8 * s2;
        float2 ar = *(const float2*)(A + j);
        float2 brv = *(const float2*)(Bm + j);
        float2 az = *(const float2*)(A + H + j);
        float2 bzv = *(const float2*)(Bm + H + j);
        float2 an = *(const float2*)(A + 2 * H + j);
        float2 bnv = *(const float2*)(Bm + 2 * H + j);
        float2 hp = *(const float2*)(g_h1s + b * H + j);
        float2 vv = *(const float2*)(g_v + j);
        {
            float r = sigf(ar.x + brv.x);
            float z = sigf(az.x + bzv.x);
            float n = tanhf(an.x + r * bnv.x);
            float hv = (1.0f - z) * n + z * hp.x;
            h1n[2 * s2] = hv; dot += hv * vv.x;
        }
        {
            float r = sigf(ar.y + brv.y);
            float z = sigf(az.y + bzv.y);
            float n = tanhf(an.y + r * bnv.y);
            float hv = (1.0f - z) * n + z * hp.y;
            h1n[2 * s2 + 1] = hv; dot += hv * vv.y;
        }
    }
    // block reduce dot
    #pragma unroll
    for (int off = 16; off > 0; off >>= 1) dot += __shfl_down_sync(0xffffffffu, dot, off);
    __shared__ float sred[8];
    __shared__ float sflags[2];
    if ((tid & 31) == 0) sred[tid >> 5] = dot;
    __syncthreads();
    if (tid == 0) {
        float d = 0.0f;
        #pragma unroll
        for (int i = 0; i < 8; ++i) d += sred[i];
        float a = g_GXF[t * B + b] + d;
        int len = lengths[b];
        float gt = (t == len - 1) ? 1.0f : sigf(a);
        int valid = (t < len);
        out[(size_t)B * T * H + (size_t)b * T + t] = valid ? gt : 0.0f;
        sflags[0] = valid ? 1.0f : 0.0f;
        sflags[1] = (valid && gt > 0.5f) ? 1.0f : 0.0f;
    }
    __syncthreads();
    bool valid = sflags[0] != 0.0f;
    bool reset = sflags[1] != 0.0f;

    float* orow = out + ((size_t)b * T + t) * H;
    #pragma unroll
    for (int s2 = 0; s2 < 2; ++s2) {
        int j = j0a + 8 * s2;
        float2 o;
        o.x = valid ? h1n[2 * s2] : 0.0f;
        o.y = valid ? h1n[2 * s2 + 1] : 0.0f;
        *(float2*)(orow + j) = o;
    }
    if (valid) {
        float ns0[4], ns1[4];
        #pragma unroll
        for (int s2 = 0; s2 < 2; ++s2) {
            int j = j0a + 8 * s2;
            float2 hi = *(const float2*)(h0 + j);
            float2 c0 = *(const float2*)(g_h0n + b * H + j);
            float n0x = reset ? hi.x : c0.x;
            float n0y = reset ? hi.y : c0.y;
            float n1x = reset ? hi.x : h1n[2 * s2];
            float n1y = reset ? hi.y : h1n[2 * s2 + 1];
            ns0[2 * s2] = n0x; ns0[2 * s2 + 1] = n0y;
            ns1[2 * s2] = n1x; ns1[2 * s2 + 1] = n1y;
            float2 w0; w0.x = n0x; w0.y = n0y;
            float2 w1; w1.x = n1x; w1.y = n1y;
            *(float2*)(g_h0s + b * H + j) = w0;
            *(float2*)(g_h1s + b * H + j) = w1;
        }
        g_h0p[(b * 64 + ks) * 4 + tc] = pack4(ns0[0], ns0[1], ns0[2], ns0[3]);
        g_h1p[(b * 64 + ks) * 4 + tc] = pack4(ns1[0], ns1[1], ns1[2], ns1[3]);
    }
}

// ---------------- host ------------------------------------------------------
extern "C" void kernel_launch(void* const* d_in, const int* in_sizes, int n_in,
                              void* d_out, int out_size)
{
    (void)in_sizes; (void)n_in; (void)out_size;
    const float* x       = (const float*)d_in[0];
    const float* h0      = (const float*)d_in[1];
    const int*   lengths = (const int*)d_in[2];
    const float* W_ih    = (const float*)d_in[3];
    const float* W_hh    = (const float*)d_in[4];
    const float* b_ih    = (const float*)d_in[5];
    const float* b_hh    = (const float*)d_in[6];
    const float* gW1     = (const float*)d_in[7];
    const float* gb1     = (const float*)d_in[8];
    const float* gW2     = (const float*)d_in[9];
    const float* gb2     = (const float*)d_in[10];
    const float* gWF     = (const float*)d_in[11];
    const float* gbF     = (const float*)d_in[12];
    float* out = (float*)d_out;

    const float* bih0 = b_ih;
    const float* bih1 = b_ih + H3;
    const float* bhh0 = b_hh;
    const float* bhh1 = b_hh + H3;

    init_kernel<<<B, 256>>>(h0);
    uvc_kernel<<<33, 64>>>(gW1, gW2, gWF, gb1, gb2, gbF);
    packw_kernel<<<dim3(H3, 4), 256>>>(W_ih, W_hh);
    packx_kernel<<<dim3(T, B), 256>>>(x);
    gxf_kernel<<<dim3(T, B), 128>>>(x);
    gi0_kernel<<<dim3(64, T), 256>>>(bih0);

    for (int t = 0; t < T; ++t) {
        l0_kernel<<<64, 256>>>(t, bhh0);
        l1_kernel<<<128, 256>>>(bih1, bhh1);
        update_kernel<<<B, 256>>>(t, lengths, h0, out);
    }
}

// round 6
// speedup vs baseline: 5.4236x; 1.3785x over previous
#include <cuda_runtime.h>
#include <cuda_fp16.h>
#include <math.h>

#define H  1024
#define H3 3072
#define B  64
#define T  256
#define LOSC   2048.0f
#define ILOSC  (1.0f/2048.0f)
#define NBLK   128

// ---------------- static scratch (no runtime allocation) -------------------
static __device__ float g_GI0[(size_t)T * B * H3];   // x@Wih0^T + bih0 (fp32)
static __device__ float g_GXF[T * B];
static __device__ float g_u[H];
static __device__ float g_v[H];
static __device__ float g_c;
static __device__ float g_h0s[B * H];                // fp32 states
static __device__ float g_h1s[B * H];
static __device__ float g_h0n[B * H];                // layer0 candidate fp32
static __device__ float g_GA[B * H3];                // gi1 raw (+bih1)
static __device__ float g_GB[B * H3];                // gh1 raw (+bhh1)

// fragment-packed hi/lo buffers: row-major rows, 256 uint4/row.
// uint4 at (row, ks, tc): k0=16ks+2tc -> {hi2(k0,k0+1), hi2(k0+8,k0+9), lo2*2048, lo2*2048}
static __device__ uint4 g_xp[(size_t)B * T * 256];   // x rows, row index b*T+t
static __device__ uint4 g_pW[4][(size_t)H3 * 256];   // 0:Wih0 1:Whh0 2:Wih1 3:Whh1
static __device__ uint4 g_h0p [B * 256];             // layer0 state packed
static __device__ uint4 g_h1p [B * 256];             // layer1 state packed
static __device__ uint4 g_h0np[B * 256];             // layer0 candidate packed

// grid barrier state
static __device__ unsigned g_barCnt;
static __device__ unsigned g_barGen;

__device__ __forceinline__ float sigf(float x) { return 1.0f / (1.0f + expf(-x)); }

__device__ __forceinline__ unsigned pk2(float a, float b) {
    __half2 h = __floats2half2_rn(a, b);
    return *reinterpret_cast<unsigned*>(&h);
}
__device__ __forceinline__ float rlo(float x) {
    return (x - __half2float(__float2half_rn(x))) * LOSC;
}
__device__ __forceinline__ uint4 pack4(float v0, float v1, float v8, float v9) {
    uint4 p;
    p.x = pk2(v0, v1);           p.y = pk2(v8, v9);
    p.z = pk2(rlo(v0), rlo(v1)); p.w = pk2(rlo(v8), rlo(v9));
    return p;
}

__device__ __forceinline__ void mma_f16(float* c, unsigned a0, unsigned a1,
                                        unsigned a2, unsigned a3,
                                        unsigned b0, unsigned b1) {
    asm volatile(
        "mma.sync.aligned.m16n8k16.row.col.f32.f16.f16.f32 "
        "{%0,%1,%2,%3}, {%4,%5,%6,%7}, {%8,%9}, {%0,%1,%2,%3};\n"
        : "+f"(c[0]), "+f"(c[1]), "+f"(c[2]), "+f"(c[3])
        : "r"(a0), "r"(a1), "r"(a2), "r"(a3), "r"(b0), "r"(b1));
}
__device__ __forceinline__ void mma3s(float* ch, float* cl, const uint4& al,
                                      const uint4& ah, const uint4& wv) {
    mma_f16(ch, al.x, ah.x, al.y, ah.y, wv.x, wv.y);
    mma_f16(cl, al.x, ah.x, al.y, ah.y, wv.z, wv.w);
    mma_f16(cl, al.z, ah.z, al.w, ah.w, wv.x, wv.y);
}

// ---------------- grid barrier (all NBLK blocks co-resident) ----------------
__device__ __forceinline__ void gbar(unsigned& gen) {
    __syncthreads();
    if (threadIdx.x == 0) {
        __threadfence();
        if (atomicAdd(&g_barCnt, 1u) == (unsigned)(NBLK - 1)) {
            g_barCnt = 0u;
            __threadfence();
            atomicExch(&g_barGen, gen + 1u);
        } else {
            while (*((volatile unsigned*)&g_barGen) < gen + 1u) { }
        }
    }
    __syncthreads();
    ++gen;
}

// ---------------- init ------------------------------------------------------
__global__ void init_kernel(const float* __restrict__ h0)
{
    int b = blockIdx.x;
    int ks = threadIdx.x >> 2, tc = threadIdx.x & 3;
    int j = ks * 16 + 2 * tc;
    float2 a = *(const float2*)(h0 + j);
    float2 c = *(const float2*)(h0 + j + 8);
    *(float2*)(g_h0s + b * H + j)     = a;
    *(float2*)(g_h0s + b * H + j + 8) = c;
    *(float2*)(g_h1s + b * H + j)     = a;
    *(float2*)(g_h1s + b * H + j + 8) = c;
    uint4 p = pack4(a.x, a.y, c.x, c.y);
    g_h0p[(b * 64 + ks) * 4 + tc] = p;
    g_h1p[(b * 64 + ks) * 4 + tc] = p;
    if (b == 0 && threadIdx.x == 0) { g_barCnt = 0u; g_barGen = 0u; }
}

// ---------------- gate folding ---------------------------------------------
__global__ void uvc_kernel(const float* __restrict__ gW1, const float* __restrict__ gW2,
                           const float* __restrict__ gWF, const float* __restrict__ gb1,
                           const float* __restrict__ gb2, const float* __restrict__ gbF)
{
    int bid = blockIdx.x;
    if (bid < 32) {
        int mat = bid >> 4, kc = bid & 15;
        const float* W = mat ? gW2 : gW1;
        float* dst = mat ? g_v : g_u;
        int k = kc * 64 + threadIdx.x;
        float s = 0.0f;
        for (int j = 0; j < H; ++j) s += gWF[j] * W[(size_t)j * H + k];
        dst[k] = s;
    } else {
        __shared__ float red[64];
        float s = 0.0f;
        for (int j = threadIdx.x; j < H; j += 64) s += gWF[j] * (gb1[j] + gb2[j]);
        red[threadIdx.x] = s;
        __syncthreads();
        for (int off = 32; off > 0; off >>= 1) {
            if (threadIdx.x < off) red[threadIdx.x] += red[threadIdx.x + off];
            __syncthreads();
        }
        if (threadIdx.x == 0) g_c = red[0] + gbF[0];
    }
}

// ---------------- gate input precompute ------------------------------------
__global__ void gxf_kernel(const float* __restrict__ x)
{
    int t = blockIdx.x, b = blockIdx.y;
    int tn = (t + 1 < T) ? (t + 1) : (T - 1);
    const float* xr = x + ((size_t)b * T + tn) * H;
    float s = 0.0f;
    for (int k = threadIdx.x; k < H; k += blockDim.x) s += xr[k] * g_u[k];
    __shared__ float red[128];
    red[threadIdx.x] = s;
    __syncthreads();
    for (int off = 64; off > 0; off >>= 1) {
        if (threadIdx.x < off) red[threadIdx.x] += red[threadIdx.x + off];
        __syncthreads();
    }
    if (threadIdx.x == 0) g_GXF[t * B + b] = red[0] + g_c;
}

// ---------------- pack weights ---------------------------------------------
__global__ void packw_kernel(const float* __restrict__ W_ih, const float* __restrict__ W_hh)
{
    int row = blockIdx.x, mat = blockIdx.y;
    int ks = threadIdx.x >> 2, tc = threadIdx.x & 3;
    const float* src = (mat == 0) ? W_ih : (mat == 1) ? W_hh
                     : (mat == 2) ? (W_ih + (size_t)H3 * H) : (W_hh + (size_t)H3 * H);
    int k0 = ks * 16 + 2 * tc;
    const float* r = src + (size_t)row * H;
    float2 a = *(const float2*)(r + k0);
    float2 c = *(const float2*)(r + k0 + 8);
    g_pW[mat][((size_t)row * 64 + ks) * 4 + tc] = pack4(a.x, a.y, c.x, c.y);
}

// ---------------- pack x ----------------------------------------------------
__global__ void packx_kernel(const float* __restrict__ x)
{
    int t = blockIdx.x, b = blockIdx.y;
    int ks = threadIdx.x >> 2, tc = threadIdx.x & 3;
    int k0 = ks * 16 + 2 * tc;
    const float* r = x + ((size_t)b * T + t) * H;
    float2 a = *(const float2*)(r + k0);
    float2 c = *(const float2*)(r + k0 + 8);
    g_xp[((size_t)(b * T + t) * 64 + ks) * 4 + tc] = pack4(a.x, a.y, c.x, c.y);
}

// ---------------- gi0: GI0[t] = x_t @ Wih0^T + bih0 (tensor) ----------------
__global__ void gi0_kernel(const float* __restrict__ bih0)
{
    int tid = threadIdx.x, w = tid >> 5, lane = tid & 31;
    int mt = w & 3, jh = w >> 2;
    int g = lane >> 2, tc = lane & 3;
    int j0 = blockIdx.x * 16, t = blockIdx.y;
    int b0 = mt * 16 + g;
    int jrow = j0 + jh * 8 + g;

    float h0a[4] = {0,0,0,0}, l0a[4] = {0,0,0,0};
    float h1a[4] = {0,0,0,0}, l1a[4] = {0,0,0,0};
    float h2a[4] = {0,0,0,0}, l2a[4] = {0,0,0,0};
    const uint4* Ap0 = g_xp + ((size_t)b0 * T + t) * 256 + tc;
    const uint4* Ap1 = Ap0 + (size_t)8 * T * 256;
    const uint4* B0 = g_pW[0] + (size_t)jrow * 256 + tc;
    const uint4* B1 = g_pW[0] + (size_t)(H + jrow) * 256 + tc;
    const uint4* B2 = g_pW[0] + (size_t)(2 * H + jrow) * 256 + tc;

    #pragma unroll 4
    for (int ks = 0; ks < 64; ++ks) {
        uint4 al = Ap0[ks * 4], ah = Ap1[ks * 4];
        uint4 w0 = B0[ks * 4], w1 = B1[ks * 4], w2 = B2[ks * 4];
        mma3s(h0a, l0a, al, ah, w0);
        mma3s(h1a, l1a, al, ah, w1);
        mma3s(h2a, l2a, al, ah, w2);
    }
    int jA = j0 + jh * 8 + 2 * tc;
    float2 br = *(const float2*)(bih0 + jA);
    float2 bz = *(const float2*)(bih0 + H + jA);
    float2 bn = *(const float2*)(bih0 + 2 * H + jA);
    #pragma unroll
    for (int rs = 0; rs < 2; ++rs) {
        int row = b0 + 8 * rs;
        float* dst = g_GI0 + ((size_t)t * B + row) * H3;
        float2 o;
        o.x = h0a[2*rs] + l0a[2*rs]*ILOSC + br.x;
        o.y = h0a[2*rs+1] + l0a[2*rs+1]*ILOSC + br.y; *(float2*)(dst + jA) = o;
        o.x = h1a[2*rs] + l1a[2*rs]*ILOSC + bz.x;
        o.y = h1a[2*rs+1] + l1a[2*rs+1]*ILOSC + bz.y; *(float2*)(dst + H + jA) = o;
        o.x = h2a[2*rs] + l2a[2*rs]*ILOSC + bn.x;
        o.y = h2a[2*rs+1] + l2a[2*rs+1]*ILOSC + bn.y; *(float2*)(dst + 2*H + jA) = o;
    }
}

// ---------------- phase bodies (device functions) ---------------------------
// NOTE: all loop-carried cross-block buffers are read with __ldcg (L2 is the
// coherence point inside one launch; L1 is NOT flushed between phases).

__device__ __forceinline__ void l0_body(int t, int j0, const float* __restrict__ bhh0,
                                        float (*s_hn)[17])
{
    int tid = threadIdx.x, w = tid >> 5, lane = tid & 31;
    int mt = w & 3, jh = w >> 2;
    int g = lane >> 2, tc = lane & 3;
    int b0 = mt * 16 + g;
    int jrow = j0 + jh * 8 + g;

    float h0a[4] = {0,0,0,0}, l0a[4] = {0,0,0,0};
    float h1a[4] = {0,0,0,0}, l1a[4] = {0,0,0,0};
    float h2a[4] = {0,0,0,0}, l2a[4] = {0,0,0,0};
    const uint4* Ap0 = g_h0p + (size_t)b0 * 256 + tc;
    const uint4* Ap1 = Ap0 + 8 * 256;
    const uint4* B0 = g_pW[1] + (size_t)jrow * 256 + tc;
    const uint4* B1 = g_pW[1] + (size_t)(H + jrow) * 256 + tc;
    const uint4* B2 = g_pW[1] + (size_t)(2 * H + jrow) * 256 + tc;

    #pragma unroll 4
    for (int ks = 0; ks < 64; ++ks) {
        uint4 al = __ldcg(Ap0 + ks * 4), ah = __ldcg(Ap1 + ks * 4);
        uint4 w0 = B0[ks * 4], w1 = B1[ks * 4], w2 = B2[ks * 4];
        mma3s(h0a, l0a, al, ah, w0);
        mma3s(h1a, l1a, al, ah, w1);
        mma3s(h2a, l2a, al, ah, w2);
    }
    int jA = j0 + jh * 8 + 2 * tc;
    float2 bhr = *(const float2*)(bhh0 + jA);
    float2 bhz = *(const float2*)(bhh0 + H + jA);
    float2 bhn = *(const float2*)(bhh0 + 2 * H + jA);
    #pragma unroll
    for (int rs = 0; rs < 2; ++rs) {
        int row = b0 + 8 * rs;
        const float* gi = g_GI0 + ((size_t)t * B + row) * H3;
        float2 gr = *(const float2*)(gi + jA);
        float2 gz = *(const float2*)(gi + H + jA);
        float2 gn = *(const float2*)(gi + 2 * H + jA);
        float2 hp = __ldcg((const float2*)(g_h0s + row * H + jA));
        float2 o;
        {
            float ar = h0a[2*rs] + l0a[2*rs]*ILOSC;
            float az = h1a[2*rs] + l1a[2*rs]*ILOSC;
            float an = h2a[2*rs] + l2a[2*rs]*ILOSC;
            float r = sigf(gr.x + ar + bhr.x);
            float z = sigf(gz.x + az + bhz.x);
            float n = tanhf(gn.x + r * (an + bhn.x));
            o.x = (1.0f - z) * n + z * hp.x;
        }
        {
            float ar = h0a[2*rs+1] + l0a[2*rs+1]*ILOSC;
            float az = h1a[2*rs+1] + l1a[2*rs+1]*ILOSC;
            float an = h2a[2*rs+1] + l2a[2*rs+1]*ILOSC;
            float r = sigf(gr.y + ar + bhr.y);
            float z = sigf(gz.y + az + bhz.y);
            float n = tanhf(gn.y + r * (an + bhn.y));
            o.y = (1.0f - z) * n + z * hp.y;
        }
        *(float2*)(g_h0n + row * H + jA) = o;
        s_hn[row][jh * 8 + 2 * tc]     = o.x;
        s_hn[row][jh * 8 + 2 * tc + 1] = o.y;
    }
    __syncthreads();
    int b = tid >> 2, tcc = tid & 3;
    int ksb = j0 >> 4;
    g_h0np[(b * 64 + ksb) * 4 + tcc] =
        pack4(s_hn[b][2 * tcc], s_hn[b][2 * tcc + 1],
              s_hn[b][2 * tcc + 8], s_hn[b][2 * tcc + 9]);
}

__device__ __forceinline__ void l1_body(int which, int j0,
                                        const float* __restrict__ bih1,
                                        const float* __restrict__ bhh1)
{
    int tid = threadIdx.x, w = tid >> 5, lane = tid & 31;
    int mt = w & 3, jh = w >> 2;
    int g = lane >> 2, tc = lane & 3;
    int b0 = mt * 16 + g;
    int jrow = j0 + jh * 8 + g;

    const uint4* A = which ? g_h1p : g_h0np;
    const uint4* W = which ? g_pW[3] : g_pW[2];
    const float* bias = which ? bhh1 : bih1;
    float* dst0 = which ? g_GB : g_GA;

    float h0a[4] = {0,0,0,0}, l0a[4] = {0,0,0,0};
    float h1a[4] = {0,0,0,0}, l1a[4] = {0,0,0,0};
    float h2a[4] = {0,0,0,0}, l2a[4] = {0,0,0,0};
    const uint4* Ap0 = A + (size_t)b0 * 256 + tc;
    const uint4* Ap1 = Ap0 + 8 * 256;
    const uint4* B0 = W + (size_t)jrow * 256 + tc;
    const uint4* B1 = W + (size_t)(H + jrow) * 256 + tc;
    const uint4* B2 = W + (size_t)(2 * H + jrow) * 256 + tc;

    #pragma unroll 4
    for (int ks = 0; ks < 64; ++ks) {
        uint4 al = __ldcg(Ap0 + ks * 4), ah = __ldcg(Ap1 + ks * 4);
        uint4 w0 = B0[ks * 4], w1 = B1[ks * 4], w2 = B2[ks * 4];
        mma3s(h0a, l0a, al, ah, w0);
        mma3s(h1a, l1a, al, ah, w1);
        mma3s(h2a, l2a, al, ah, w2);
    }
    int jA = j0 + jh * 8 + 2 * tc;
    float2 br = *(const float2*)(bias + jA);
    float2 bz = *(const float2*)(bias + H + jA);
    float2 bn = *(const float2*)(bias + 2 * H + jA);
    #pragma unroll
    for (int rs = 0; rs < 2; ++rs) {
        int row = b0 + 8 * rs;
        float* dst = dst0 + (size_t)row * H3;
        float2 o;
        o.x = h0a[2*rs] + l0a[2*rs]*ILOSC + br.x;
        o.y = h0a[2*rs+1] + l0a[2*rs+1]*ILOSC + br.y; *(float2*)(dst + jA) = o;
        o.x = h1a[2*rs] + l1a[2*rs]*ILOSC + bz.x;
        o.y = h1a[2*rs+1] + l1a[2*rs+1]*ILOSC + bz.y; *(float2*)(dst + H + jA) = o;
        o.x = h2a[2*rs] + l2a[2*rs]*ILOSC + bn.x;
        o.y = h2a[2*rs+1] + l2a[2*rs+1]*ILOSC + bn.y; *(float2*)(dst + 2*H + jA) = o;
    }
}

__device__ __forceinline__ void update_body(int t, int b,
                                            const int* __restrict__ lengths,
                                            const float* __restrict__ h0,
                                            float* __restrict__ out,
                                            float* s_red, float* s_flags)
{
    int tid = threadIdx.x;
    int ks = tid >> 2, tc = tid & 3;
    int j0a = ks * 16 + 2 * tc;
    const float* A  = g_GA + (size_t)b * H3;
    const float* Bm = g_GB + (size_t)b * H3;

    float h1n[4];
    float dot = 0.0f;
    #pragma unroll
    for (int s2 = 0; s2 < 2; ++s2) {
        int j = j0a + 8 * s2;
        float2 ar  = __ldcg((const float2*)(A + j));
        float2 brv = __ldcg((const float2*)(Bm + j));
        float2 az  = __ldcg((const float2*)(A + H + j));
        float2 bzv = __ldcg((const float2*)(Bm + H + j));
        float2 an  = __ldcg((const float2*)(A + 2 * H + j));
        float2 bnv = __ldcg((const float2*)(Bm + 2 * H + j));
        float2 hp  = __ldcg((const float2*)(g_h1s + b * H + j));
        float2 vv = *(const float2*)(g_v + j);
        {
            float r = sigf(ar.x + brv.x);
            float z = sigf(az.x + bzv.x);
            float n = tanhf(an.x + r * bnv.x);
            float hv = (1.0f - z) * n + z * hp.x;
            h1n[2 * s2] = hv; dot += hv * vv.x;
        }
        {
            float r = sigf(ar.y + brv.y);
            float z = sigf(az.y + bzv.y);
            float n = tanhf(an.y + r * bnv.y);
            float hv = (1.0f - z) * n + z * hp.y;
            h1n[2 * s2 + 1] = hv; dot += hv * vv.y;
        }
    }
    #pragma unroll
    for (int off = 16; off > 0; off >>= 1) dot += __shfl_down_sync(0xffffffffu, dot, off);
    if ((tid & 31) == 0) s_red[tid >> 5] = dot;
    __syncthreads();
    if (tid == 0) {
        float d = 0.0f;
        #pragma unroll
        for (int i = 0; i < 8; ++i) d += s_red[i];
        float a = g_GXF[t * B + b] + d;
        int len = lengths[b];
        float gt = (t == len - 1) ? 1.0f : sigf(a);
        int valid = (t < len);
        out[(size_t)B * T * H + (size_t)b * T + t] = valid ? gt : 0.0f;
        s_flags[0] = valid ? 1.0f : 0.0f;
        s_flags[1] = (valid && gt > 0.5f) ? 1.0f : 0.0f;
    }
    __syncthreads();
    bool valid = s_flags[0] != 0.0f;
    bool reset = s_flags[1] != 0.0f;

    float* orow = out + ((size_t)b * T + t) * H;
    #pragma unroll
    for (int s2 = 0; s2 < 2; ++s2) {
        int j = j0a + 8 * s2;
        float2 o;
        o.x = valid ? h1n[2 * s2] : 0.0f;
        o.y = valid ? h1n[2 * s2 + 1] : 0.0f;
        *(float2*)(orow + j) = o;
    }
    if (valid) {
        float ns0[4], ns1[4];
        #pragma unroll
        for (int s2 = 0; s2 < 2; ++s2) {
            int j = j0a + 8 * s2;
            float2 hi = *(const float2*)(h0 + j);
            float2 c0 = __ldcg((const float2*)(g_h0n + b * H + j));
            float n0x = reset ? hi.x : c0.x;
            float n0y = reset ? hi.y : c0.y;
            float n1x = reset ? hi.x : h1n[2 * s2];
            float n1y = reset ? hi.y : h1n[2 * s2 + 1];
            ns0[2 * s2] = n0x; ns0[2 * s2 + 1] = n0y;
            ns1[2 * s2] = n1x; ns1[2 * s2 + 1] = n1y;
            float2 w0; w0.x = n0x; w0.y = n0y;
            float2 w1; w1.x = n1x; w1.y = n1y;
            *(float2*)(g_h0s + b * H + j) = w0;
            *(float2*)(g_h1s + b * H + j) = w1;
        }
        g_h0p[(b * 64 + ks) * 4 + tc] = pack4(ns0[0], ns0[1], ns0[2], ns0[3]);
        g_h1p[(b * 64 + ks) * 4 + tc] = pack4(ns1[0], ns1[1], ns1[2], ns1[3]);
    }
}

// ---------------- persistent loop kernel ------------------------------------
__global__ void __launch_bounds__(256, 1)
loop_kernel(const int* __restrict__ lengths, const float* __restrict__ h0,
            float* __restrict__ out, const float* __restrict__ bhh0,
            const float* __restrict__ bih1, const float* __restrict__ bhh1)
{
    __shared__ float s_hn[64][17];
    __shared__ float s_red[8];
    __shared__ float s_flags[2];
    int blk = blockIdx.x;
    unsigned gen = 0;

    for (int t = 0; t < T; ++t) {
        if (blk < 64) l0_body(t, blk * 16, bhh0, s_hn);
        gbar(gen);
        l1_body(blk >> 6, (blk & 63) * 16, bih1, bhh1);
        gbar(gen);
        if (blk < 64) update_body(t, blk, lengths, h0, out, s_red, s_flags);
        gbar(gen);
    }
}

// ---------------- host ------------------------------------------------------
extern "C" void kernel_launch(void* const* d_in, const int* in_sizes, int n_in,
                              void* d_out, int out_size)
{
    (void)in_sizes; (void)n_in; (void)out_size;
    const float* x       = (const float*)d_in[0];
    const float* h0      = (const float*)d_in[1];
    const int*   lengths = (const int*)d_in[2];
    const float* W_ih    = (const float*)d_in[3];
    const float* W_hh    = (const float*)d_in[4];
    const float* b_ih    = (const float*)d_in[5];
    const float* b_hh    = (const float*)d_in[6];
    const float* gW1     = (const float*)d_in[7];
    const float* gb1     = (const float*)d_in[8];
    const float* gW2     = (const float*)d_in[9];
    const float* gb2     = (const float*)d_in[10];
    const float* gWF     = (const float*)d_in[11];
    const float* gbF     = (const float*)d_in[12];
    float* out = (float*)d_out;

    const float* bih0 = b_ih;
    const float* bih1 = b_ih + H3;
    const float* bhh0 = b_hh;
    const float* bhh1 = b_hh + H3;

    init_kernel<<<B, 256>>>(h0);
    uvc_kernel<<<33, 64>>>(gW1, gW2, gWF, gb1, gb2, gbF);
    packw_kernel<<<dim3(H3, 4), 256>>>(W_ih, W_hh);
    packx_kernel<<<dim3(T, B), 256>>>(x);
    gxf_kernel<<<dim3(T, B), 128>>>(x);
    gi0_kernel<<<dim3(64, T), 256>>>(bih0);

    loop_kernel<<<NBLK, 256>>>(lengths, h0, out, bhh0, bih1, bhh1);
}

// round 7
// speedup vs baseline: 6.4760x; 1.1940x over previous
#include <cuda_runtime.h>
#include <cuda_fp16.h>
#include <math.h>

#define H  1024
#define H3 3072
#define B  64
#define T  256
#define LOSC   2048.0f
#define ILOSC  (1.0f/2048.0f)
#define NBLK   128

// ---------------- static scratch (no runtime allocation) -------------------
static __device__ float g_GI0[(size_t)T * B * H3];   // x@Wih0^T + bih0 (fp32)
static __device__ float g_GXF[T * B];
static __device__ float g_u[H];
static __device__ float g_v[H];
static __device__ float g_c;
static __device__ float g_h0s[B * H];                // fp32 states
static __device__ float g_h1s[B * H];
static __device__ float g_h0n[B * H];                // layer0 candidate fp32
static __device__ float g_GA[B * H3];                // gi1 raw (+bih1)
static __device__ float g_GB[B * H3];                // gh1 raw (+bhh1)

// fragment-packed hi/lo buffers: row-major rows, 256 uint4/row.
// uint4 at (row, ks, tc): k0=16ks+2tc -> {hi2(k0,k0+1), hi2(k0+8,k0+9), lo2*2048, lo2*2048}
static __device__ uint4 g_xp[(size_t)B * T * 256];   // x rows, row index b*T+t
static __device__ uint4 g_pW[4][(size_t)H3 * 256];   // 0:Wih0 1:Whh0 2:Wih1 3:Whh1
static __device__ uint4 g_h0p [B * 256];             // layer0 state packed
static __device__ uint4 g_h1p [B * 256];             // layer1 state packed
static __device__ uint4 g_h0np[B * 256];             // layer0 candidate packed

// grid barrier state
static __device__ unsigned g_barCnt;
static __device__ unsigned g_barGen;

__device__ __forceinline__ float sigf(float x) { return 1.0f / (1.0f + expf(-x)); }

__device__ __forceinline__ unsigned pk2(float a, float b) {
    __half2 h = __floats2half2_rn(a, b);
    return *reinterpret_cast<unsigned*>(&h);
}
__device__ __forceinline__ float rlo(float x) {
    return (x - __half2float(__float2half_rn(x))) * LOSC;
}
__device__ __forceinline__ uint4 pack4(float v0, float v1, float v8, float v9) {
    uint4 p;
    p.x = pk2(v0, v1);           p.y = pk2(v8, v9);
    p.z = pk2(rlo(v0), rlo(v1)); p.w = pk2(rlo(v8), rlo(v9));
    return p;
}

__device__ __forceinline__ void mma_f16(float* c, unsigned a0, unsigned a1,
                                        unsigned a2, unsigned a3,
                                        unsigned b0, unsigned b1) {
    asm volatile(
        "mma.sync.aligned.m16n8k16.row.col.f32.f16.f16.f32 "
        "{%0,%1,%2,%3}, {%4,%5,%6,%7}, {%8,%9}, {%0,%1,%2,%3};\n"
        : "+f"(c[0]), "+f"(c[1]), "+f"(c[2]), "+f"(c[3])
        : "r"(a0), "r"(a1), "r"(a2), "r"(a3), "r"(b0), "r"(b1));
}
__device__ __forceinline__ void mma3s(float* ch, float* cl, const uint4& al,
                                      const uint4& ah, const uint4& wv) {
    mma_f16(ch, al.x, ah.x, al.y, ah.y, wv.x, wv.y);
    mma_f16(cl, al.x, ah.x, al.y, ah.y, wv.z, wv.w);
    mma_f16(cl, al.z, ah.z, al.w, ah.w, wv.x, wv.y);
}

// ---------------- grid barrier (all NBLK blocks co-resident) ----------------
__device__ __forceinline__ void gbar(unsigned& gen) {
    __syncthreads();
    if (threadIdx.x == 0) {
        __threadfence();
        if (atomicAdd(&g_barCnt, 1u) == (unsigned)(NBLK - 1)) {
            g_barCnt = 0u;
            __threadfence();
            atomicExch(&g_barGen, gen + 1u);
        } else {
            while (*((volatile unsigned*)&g_barGen) < gen + 1u) __nanosleep(64);
        }
    }
    __syncthreads();
    ++gen;
}

// ---------------- init ------------------------------------------------------
__global__ void init_kernel(const float* __restrict__ h0)
{
    int b = blockIdx.x;
    int ks = threadIdx.x >> 2, tc = threadIdx.x & 3;
    int j = ks * 16 + 2 * tc;
    float2 a = *(const float2*)(h0 + j);
    float2 c = *(const float2*)(h0 + j + 8);
    *(float2*)(g_h0s + b * H + j)     = a;
    *(float2*)(g_h0s + b * H + j + 8) = c;
    *(float2*)(g_h1s + b * H + j)     = a;
    *(float2*)(g_h1s + b * H + j + 8) = c;
    uint4 p = pack4(a.x, a.y, c.x, c.y);
    g_h0p[(b * 64 + ks) * 4 + tc] = p;
    g_h1p[(b * 64 + ks) * 4 + tc] = p;
    if (b == 0 && threadIdx.x == 0) { g_barCnt = 0u; g_barGen = 0u; }
}

// ---------------- gate folding ---------------------------------------------
__global__ void uvc_kernel(const float* __restrict__ gW1, const float* __restrict__ gW2,
                           const float* __restrict__ gWF, const float* __restrict__ gb1,
                           const float* __restrict__ gb2, const float* __restrict__ gbF)
{
    int bid = blockIdx.x;
    if (bid < 32) {
        int mat = bid >> 4, kc = bid & 15;
        const float* W = mat ? gW2 : gW1;
        float* dst = mat ? g_v : g_u;
        int k = kc * 64 + threadIdx.x;
        float s = 0.0f;
        for (int j = 0; j < H; ++j) s += gWF[j] * W[(size_t)j * H + k];
        dst[k] = s;
    } else {
        __shared__ float red[64];
        float s = 0.0f;
        for (int j = threadIdx.x; j < H; j += 64) s += gWF[j] * (gb1[j] + gb2[j]);
        red[threadIdx.x] = s;
        __syncthreads();
        for (int off = 32; off > 0; off >>= 1) {
            if (threadIdx.x < off) red[threadIdx.x] += red[threadIdx.x + off];
            __syncthreads();
        }
        if (threadIdx.x == 0) g_c = red[0] + gbF[0];
    }
}

// ---------------- gate input precompute ------------------------------------
__global__ void gxf_kernel(const float* __restrict__ x)
{
    int t = blockIdx.x, b = blockIdx.y;
    int tn = (t + 1 < T) ? (t + 1) : (T - 1);
    const float* xr = x + ((size_t)b * T + tn) * H;
    float s = 0.0f;
    for (int k = threadIdx.x; k < H; k += blockDim.x) s += xr[k] * g_u[k];
    __shared__ float red[128];
    red[threadIdx.x] = s;
    __syncthreads();
    for (int off = 64; off > 0; off >>= 1) {
        if (threadIdx.x < off) red[threadIdx.x] += red[threadIdx.x + off];
        __syncthreads();
    }
    if (threadIdx.x == 0) g_GXF[t * B + b] = red[0] + g_c;
}

// ---------------- pack weights ---------------------------------------------
__global__ void packw_kernel(const float* __restrict__ W_ih, const float* __restrict__ W_hh)
{
    int row = blockIdx.x, mat = blockIdx.y;
    int ks = threadIdx.x >> 2, tc = threadIdx.x & 3;
    const float* src = (mat == 0) ? W_ih : (mat == 1) ? W_hh
                     : (mat == 2) ? (W_ih + (size_t)H3 * H) : (W_hh + (size_t)H3 * H);
    int k0 = ks * 16 + 2 * tc;
    const float* r = src + (size_t)row * H;
    float2 a = *(const float2*)(r + k0);
    float2 c = *(const float2*)(r + k0 + 8);
    g_pW[mat][((size_t)row * 64 + ks) * 4 + tc] = pack4(a.x, a.y, c.x, c.y);
}

// ---------------- pack x ----------------------------------------------------
__global__ void packx_kernel(const float* __restrict__ x)
{
    int t = blockIdx.x, b = blockIdx.y;
    int ks = threadIdx.x >> 2, tc = threadIdx.x & 3;
    int k0 = ks * 16 + 2 * tc;
    const float* r = x + ((size_t)b * T + t) * H;
    float2 a = *(const float2*)(r + k0);
    float2 c = *(const float2*)(r + k0 + 8);
    g_xp[((size_t)(b * T + t) * 64 + ks) * 4 + tc] = pack4(a.x, a.y, c.x, c.y);
}

// ---------------- gi0: GI0[t] = x_t @ Wih0^T + bih0 (tensor) ----------------
__global__ void gi0_kernel(const float* __restrict__ bih0)
{
    int tid = threadIdx.x, w = tid >> 5, lane = tid & 31;
    int mt = w & 3, jh = w >> 2;
    int g = lane >> 2, tc = lane & 3;
    int j0 = blockIdx.x * 16, t = blockIdx.y;
    int b0 = mt * 16 + g;
    int jrow = j0 + jh * 8 + g;

    float h0a[4] = {0,0,0,0}, l0a[4] = {0,0,0,0};
    float h1a[4] = {0,0,0,0}, l1a[4] = {0,0,0,0};
    float h2a[4] = {0,0,0,0}, l2a[4] = {0,0,0,0};
    const uint4* Ap0 = g_xp + ((size_t)b0 * T + t) * 256 + tc;
    const uint4* Ap1 = Ap0 + (size_t)8 * T * 256;
    const uint4* B0 = g_pW[0] + (size_t)jrow * 256 + tc;
    const uint4* B1 = g_pW[0] + (size_t)(H + jrow) * 256 + tc;
    const uint4* B2 = g_pW[0] + (size_t)(2 * H + jrow) * 256 + tc;

    #pragma unroll 4
    for (int ks = 0; ks < 64; ++ks) {
        uint4 al = Ap0[ks * 4], ah = Ap1[ks * 4];
        uint4 w0 = B0[ks * 4], w1 = B1[ks * 4], w2 = B2[ks * 4];
        mma3s(h0a, l0a, al, ah, w0);
        mma3s(h1a, l1a, al, ah, w1);
        mma3s(h2a, l2a, al, ah, w2);
    }
    int jA = j0 + jh * 8 + 2 * tc;
    float2 br = *(const float2*)(bih0 + jA);
    float2 bz = *(const float2*)(bih0 + H + jA);
    float2 bn = *(const float2*)(bih0 + 2 * H + jA);
    #pragma unroll
    for (int rs = 0; rs < 2; ++rs) {
        int row = b0 + 8 * rs;
        float* dst = g_GI0 + ((size_t)t * B + row) * H3;
        float2 o;
        o.x = h0a[2*rs] + l0a[2*rs]*ILOSC + br.x;
        o.y = h0a[2*rs+1] + l0a[2*rs+1]*ILOSC + br.y; *(float2*)(dst + jA) = o;
        o.x = h1a[2*rs] + l1a[2*rs]*ILOSC + bz.x;
        o.y = h1a[2*rs+1] + l1a[2*rs+1]*ILOSC + bz.y; *(float2*)(dst + H + jA) = o;
        o.x = h2a[2*rs] + l2a[2*rs]*ILOSC + bn.x;
        o.y = h2a[2*rs+1] + l2a[2*rs+1]*ILOSC + bn.y; *(float2*)(dst + 2*H + jA) = o;
    }
}

// ---------------- phase bodies (device functions) ---------------------------
// All loop-carried cross-block buffers are read with __ldcg (L2 coherence;
// L1 is NOT flushed between phases inside one launch).

__device__ __forceinline__ void l0_body(int t, int j0, const float* __restrict__ bhh0,
                                        float (*s_hn)[17])
{
    int tid = threadIdx.x, w = tid >> 5, lane = tid & 31;
    int mt = w & 3, jh = w >> 2;
    int g = lane >> 2, tc = lane & 3;
    int b0 = mt * 16 + g;
    int jrow = j0 + jh * 8 + g;

    float h0a[4] = {0,0,0,0}, l0a[4] = {0,0,0,0};
    float h1a[4] = {0,0,0,0}, l1a[4] = {0,0,0,0};
    float h2a[4] = {0,0,0,0}, l2a[4] = {0,0,0,0};
    const uint4* Ap0 = g_h0p + (size_t)b0 * 256 + tc;
    const uint4* Ap1 = Ap0 + 8 * 256;
    const uint4* B0 = g_pW[1] + (size_t)jrow * 256 + tc;
    const uint4* B1 = g_pW[1] + (size_t)(H + jrow) * 256 + tc;
    const uint4* B2 = g_pW[1] + (size_t)(2 * H + jrow) * 256 + tc;

    #pragma unroll 4
    for (int ks = 0; ks < 64; ++ks) {
        uint4 al = __ldcg(Ap0 + ks * 4), ah = __ldcg(Ap1 + ks * 4);
        uint4 w0 = B0[ks * 4], w1 = B1[ks * 4], w2 = B2[ks * 4];
        mma3s(h0a, l0a, al, ah, w0);
        mma3s(h1a, l1a, al, ah, w1);
        mma3s(h2a, l2a, al, ah, w2);
    }
    int jA = j0 + jh * 8 + 2 * tc;
    float2 bhr = *(const float2*)(bhh0 + jA);
    float2 bhz = *(const float2*)(bhh0 + H + jA);
    float2 bhn = *(const float2*)(bhh0 + 2 * H + jA);
    #pragma unroll
    for (int rs = 0; rs < 2; ++rs) {
        int row = b0 + 8 * rs;
        const float* gi = g_GI0 + ((size_t)t * B + row) * H3;
        float2 gr = *(const float2*)(gi + jA);
        float2 gz = *(const float2*)(gi + H + jA);
        float2 gn = *(const float2*)(gi + 2 * H + jA);
        float2 hp = __ldcg((const float2*)(g_h0s + row * H + jA));
        float2 o;
        {
            float ar = h0a[2*rs] + l0a[2*rs]*ILOSC;
            float az = h1a[2*rs] + l1a[2*rs]*ILOSC;
            float an = h2a[2*rs] + l2a[2*rs]*ILOSC;
            float r = sigf(gr.x + ar + bhr.x);
            float z = sigf(gz.x + az + bhz.x);
            float n = tanhf(gn.x + r * (an + bhn.x));
            o.x = (1.0f - z) * n + z * hp.x;
        }
        {
            float ar = h0a[2*rs+1] + l0a[2*rs+1]*ILOSC;
            float az = h1a[2*rs+1] + l1a[2*rs+1]*ILOSC;
            float an = h2a[2*rs+1] + l2a[2*rs+1]*ILOSC;
            float r = sigf(gr.y + ar + bhr.y);
            float z = sigf(gz.y + az + bhz.y);
            float n = tanhf(gn.y + r * (an + bhn.y));
            o.y = (1.0f - z) * n + z * hp.y;
        }
        *(float2*)(g_h0n + row * H + jA) = o;
        s_hn[row][jh * 8 + 2 * tc]     = o.x;
        s_hn[row][jh * 8 + 2 * tc + 1] = o.y;
    }
    __syncthreads();
    int b = tid >> 2, tcc = tid & 3;
    int ksb = j0 >> 4;
    g_h0np[(b * 64 + ksb) * 4 + tcc] =
        pack4(s_hn[b][2 * tcc], s_hn[b][2 * tcc + 1],
              s_hn[b][2 * tcc + 8], s_hn[b][2 * tcc + 9]);
}

// hh-part of layer1: GB = h1p @ Whh1^T + bhh1 (full M, full K, 16-j tile)
__device__ __forceinline__ void l1hh_body(int j0, const float* __restrict__ bhh1)
{
    int tid = threadIdx.x, w = tid >> 5, lane = tid & 31;
    int mt = w & 3, jh = w >> 2;
    int g = lane >> 2, tc = lane & 3;
    int b0 = mt * 16 + g;
    int jrow = j0 + jh * 8 + g;

    float h0a[4] = {0,0,0,0}, l0a[4] = {0,0,0,0};
    float h1a[4] = {0,0,0,0}, l1a[4] = {0,0,0,0};
    float h2a[4] = {0,0,0,0}, l2a[4] = {0,0,0,0};
    const uint4* Ap0 = g_h1p + (size_t)b0 * 256 + tc;
    const uint4* Ap1 = Ap0 + 8 * 256;
    const uint4* B0 = g_pW[3] + (size_t)jrow * 256 + tc;
    const uint4* B1 = g_pW[3] + (size_t)(H + jrow) * 256 + tc;
    const uint4* B2 = g_pW[3] + (size_t)(2 * H + jrow) * 256 + tc;

    #pragma unroll 4
    for (int ks = 0; ks < 64; ++ks) {
        uint4 al = __ldcg(Ap0 + ks * 4), ah = __ldcg(Ap1 + ks * 4);
        uint4 w0 = B0[ks * 4], w1 = B1[ks * 4], w2 = B2[ks * 4];
        mma3s(h0a, l0a, al, ah, w0);
        mma3s(h1a, l1a, al, ah, w1);
        mma3s(h2a, l2a, al, ah, w2);
    }
    int jA = j0 + jh * 8 + 2 * tc;
    float2 br = *(const float2*)(bhh1 + jA);
    float2 bz = *(const float2*)(bhh1 + H + jA);
    float2 bn = *(const float2*)(bhh1 + 2 * H + jA);
    #pragma unroll
    for (int rs = 0; rs < 2; ++rs) {
        int row = b0 + 8 * rs;
        float* dst = g_GB + (size_t)row * H3;
        float2 o;
        o.x = h0a[2*rs] + l0a[2*rs]*ILOSC + br.x;
        o.y = h0a[2*rs+1] + l0a[2*rs+1]*ILOSC + br.y; *(float2*)(dst + jA) = o;
        o.x = h1a[2*rs] + l1a[2*rs]*ILOSC + bz.x;
        o.y = h1a[2*rs+1] + l1a[2*rs+1]*ILOSC + bz.y; *(float2*)(dst + H + jA) = o;
        o.x = h2a[2*rs] + l2a[2*rs]*ILOSC + bn.x;
        o.y = h2a[2*rs+1] + l2a[2*rs+1]*ILOSC + bn.y; *(float2*)(dst + 2*H + jA) = o;
    }
}

// ih-part of layer1 across ALL 128 blocks: GA = h0np @ Wih1^T + bih1.
// Block: (mhalf = blk>>6) x (j-tile = blk&63). Warps: mt=w&1, jh=(w>>1)&1, kh=w>>2.
// K split across warp pairs; combine via SMEM.
__device__ __forceinline__ void l1ih_body(int mhalf, int j0,
                                          const float* __restrict__ bih1,
                                          float* s_comb)
{
    int tid = threadIdx.x, w = tid >> 5, lane = tid & 31;
    int mt = w & 1, jh = (w >> 1) & 1, kh = w >> 2;
    int g = lane >> 2, tc = lane & 3;
    int b0 = mhalf * 32 + mt * 16 + g;
    int jrow = j0 + jh * 8 + g;

    float h0a[4] = {0,0,0,0}, l0a[4] = {0,0,0,0};
    float h1a[4] = {0,0,0,0}, l1a[4] = {0,0,0,0};
    float h2a[4] = {0,0,0,0}, l2a[4] = {0,0,0,0};
    const uint4* Ap0 = g_h0np + (size_t)b0 * 256 + tc;
    const uint4* Ap1 = Ap0 + 8 * 256;
    const uint4* B0 = g_pW[2] + (size_t)jrow * 256 + tc;
    const uint4* B1 = g_pW[2] + (size_t)(H + jrow) * 256 + tc;
    const uint4* B2 = g_pW[2] + (size_t)(2 * H + jrow) * 256 + tc;

    int ksb = kh * 32;
    #pragma unroll 4
    for (int ks = ksb; ks < ksb + 32; ++ks) {
        uint4 al = __ldcg(Ap0 + ks * 4), ah = __ldcg(Ap1 + ks * 4);
        uint4 w0 = B0[ks * 4], w1 = B1[ks * 4], w2 = B2[ks * 4];
        mma3s(h0a, l0a, al, ah, w0);
        mma3s(h1a, l1a, al, ah, w1);
        mma3s(h2a, l2a, al, ah, w2);
    }
    float v[12];
    #pragma unroll
    for (int i = 0; i < 4; ++i) {
        v[i]     = h0a[i] + l0a[i] * ILOSC;
        v[4 + i] = h1a[i] + l1a[i] * ILOSC;
        v[8 + i] = h2a[i] + l2a[i] * ILOSC;
    }
    int combo = w & 3;                      // (jh<<1)|mt
    float* slot = s_comb + (combo * 32 + lane) * 12;
    if (kh == 1) {
        #pragma unroll
        for (int i = 0; i < 12; ++i) slot[i] = v[i];
    }
    __syncthreads();
    if (kh == 0) {
        #pragma unroll
        for (int i = 0; i < 12; ++i) v[i] += slot[i];
        int jA = j0 + jh * 8 + 2 * tc;
        float2 br = *(const float2*)(bih1 + jA);
        float2 bz = *(const float2*)(bih1 + H + jA);
        float2 bn = *(const float2*)(bih1 + 2 * H + jA);
        #pragma unroll
        for (int rs = 0; rs < 2; ++rs) {
            int row = b0 + 8 * rs;
            float* dst = g_GA + (size_t)row * H3;
            float2 o;
            o.x = v[2*rs]   + br.x; o.y = v[2*rs+1]   + br.y; *(float2*)(dst + jA) = o;
            o.x = v[4+2*rs] + bz.x; o.y = v[4+2*rs+1] + bz.y; *(float2*)(dst + H + jA) = o;
            o.x = v[8+2*rs] + bn.x; o.y = v[8+2*rs+1] + bn.y; *(float2*)(dst + 2*H + jA) = o;
        }
    }
    __syncthreads();
}

__device__ __forceinline__ void update_body(int t, int b,
                                            const int* __restrict__ lengths,
                                            const float* __restrict__ h0,
                                            float* __restrict__ out,
                                            float* s_red, float* s_flags)
{
    int tid = threadIdx.x;
    int ks = tid >> 2, tc = tid & 3;
    int j0a = ks * 16 + 2 * tc;
    const float* A  = g_GA + (size_t)b * H3;
    const float* Bm = g_GB + (size_t)b * H3;

    float h1n[4];
    float dot = 0.0f;
    #pragma unroll
    for (int s2 = 0; s2 < 2; ++s2) {
        int j = j0a + 8 * s2;
        float2 ar  = __ldcg((const float2*)(A + j));
        float2 brv = __ldcg((const float2*)(Bm + j));
        float2 az  = __ldcg((const float2*)(A + H + j));
        float2 bzv = __ldcg((const float2*)(Bm + H + j));
        float2 an  = __ldcg((const float2*)(A + 2 * H + j));
        float2 bnv = __ldcg((const float2*)(Bm + 2 * H + j));
        float2 hp  = __ldcg((const float2*)(g_h1s + b * H + j));
        float2 vv = *(const float2*)(g_v + j);
        {
            float r = sigf(ar.x + brv.x);
            float z = sigf(az.x + bzv.x);
            float n = tanhf(an.x + r * bnv.x);
            float hv = (1.0f - z) * n + z * hp.x;
            h1n[2 * s2] = hv; dot += hv * vv.x;
        }
        {
            float r = sigf(ar.y + brv.y);
            float z = sigf(az.y + bzv.y);
            float n = tanhf(an.y + r * bnv.y);
            float hv = (1.0f - z) * n + z * hp.y;
            h1n[2 * s2 + 1] = hv; dot += hv * vv.y;
        }
    }
    #pragma unroll
    for (int off = 16; off > 0; off >>= 1) dot += __shfl_down_sync(0xffffffffu, dot, off);
    if ((tid & 31) == 0) s_red[tid >> 5] = dot;
    __syncthreads();
    if (tid == 0) {
        float d = 0.0f;
        #pragma unroll
        for (int i = 0; i < 8; ++i) d += s_red[i];
        float a = g_GXF[t * B + b] + d;
        int len = lengths[b];
        float gt = (t == len - 1) ? 1.0f : sigf(a);
        int valid = (t < len);
        out[(size_t)B * T * H + (size_t)b * T + t] = valid ? gt : 0.0f;
        s_flags[0] = valid ? 1.0f : 0.0f;
        s_flags[1] = (valid && gt > 0.5f) ? 1.0f : 0.0f;
    }
    __syncthreads();
    bool valid = s_flags[0] != 0.0f;
    bool reset = s_flags[1] != 0.0f;

    float* orow = out + ((size_t)b * T + t) * H;
    #pragma unroll
    for (int s2 = 0; s2 < 2; ++s2) {
        int j = j0a + 8 * s2;
        float2 o;
        o.x = valid ? h1n[2 * s2] : 0.0f;
        o.y = valid ? h1n[2 * s2 + 1] : 0.0f;
        *(float2*)(orow + j) = o;
    }
    if (valid) {
        float ns0[4], ns1[4];
        #pragma unroll
        for (int s2 = 0; s2 < 2; ++s2) {
            int j = j0a + 8 * s2;
            float2 hi = *(const float2*)(h0 + j);
            float2 c0 = __ldcg((const float2*)(g_h0n + b * H + j));
            float n0x = reset ? hi.x : c0.x;
            float n0y = reset ? hi.y : c0.y;
            float n1x = reset ? hi.x : h1n[2 * s2];
            float n1y = reset ? hi.y : h1n[2 * s2 + 1];
            ns0[2 * s2] = n0x; ns0[2 * s2 + 1] = n0y;
            ns1[2 * s2] = n1x; ns1[2 * s2 + 1] = n1y;
            float2 w0; w0.x = n0x; w0.y = n0y;
            float2 w1; w1.x = n1x; w1.y = n1y;
            *(float2*)(g_h0s + b * H + j) = w0;
            *(float2*)(g_h1s + b * H + j) = w1;
        }
        g_h0p[(b * 64 + ks) * 4 + tc] = pack4(ns0[0], ns0[1], ns0[2], ns0[3]);
        g_h1p[(b * 64 + ks) * 4 + tc] = pack4(ns1[0], ns1[1], ns1[2], ns1[3]);
    }
}

// ---------------- persistent loop kernel ------------------------------------
__global__ void __launch_bounds__(256, 1)
loop_kernel(const int* __restrict__ lengths, const float* __restrict__ h0,
            float* __restrict__ out, const float* __restrict__ bhh0,
            const float* __restrict__ bih1, const float* __restrict__ bhh1)
{
    __shared__ float s_hn[64][17];
    __shared__ float s_comb[4 * 32 * 12];
    __shared__ float s_red[8];
    __shared__ float s_flags[2];
    int blk = blockIdx.x;
    unsigned gen = 0;

    for (int t = 0; t < T; ++t) {
        // phase 1: l0 (blocks 0-63) || l1-hh GEMM (blocks 64-127, indep of l0)
        if (blk < 64) l0_body(t, blk * 16, bhh0, s_hn);
        else          l1hh_body((blk - 64) * 16, bhh1);
        gbar(gen);
        // phase 2: l1-ih GEMM across all 128 blocks (m-half x j-tile, k-split)
        l1ih_body(blk >> 6, (blk & 63) * 16, bih1, s_comb);
        gbar(gen);
        // phase 3: gate + state update
        if (blk < 64) update_body(t, blk, lengths, h0, out, s_red, s_flags);
        gbar(gen);
    }
}

// ---------------- host ------------------------------------------------------
extern "C" void kernel_launch(void* const* d_in, const int* in_sizes, int n_in,
                              void* d_out, int out_size)
{
    (void)in_sizes; (void)n_in; (void)out_size;
    const float* x       = (const float*)d_in[0];
    const float* h0      = (const float*)d_in[1];
    const int*   lengths = (const int*)d_in[2];
    const float* W_ih    = (const float*)d_in[3];
    const float* W_hh    = (const float*)d_in[4];
    const float* b_ih    = (const float*)d_in[5];
    const float* b_hh    = (const float*)d_in[6];
    const float* gW1     = (const float*)d_in[7];
    const float* gb1     = (const float*)d_in[8];
    const float* gW2     = (const float*)d_in[9];
    const float* gb2     = (const float*)d_in[10];
    const float* gWF     = (const float*)d_in[11];
    const float* gbF     = (const float*)d_in[12];
    float* out = (float*)d_out;

    const float* bih0 = b_ih;
    const float* bih1 = b_ih + H3;
    const float* bhh0 = b_hh;
    const float* bhh1 = b_hh + H3;

    init_kernel<<<B, 256>>>(h0);
    uvc_kernel<<<33, 64>>>(gW1, gW2, gWF, gb1, gb2, gbF);
    packw_kernel<<<dim3(H3, 4), 256>>>(W_ih, W_hh);
    packx_kernel<<<dim3(T, B), 256>>>(x);
    gxf_kernel<<<dim3(T, B), 128>>>(x);
    gi0_kernel<<<dim3(64, T), 256>>>(bih0);

    loop_kernel<<<NBLK, 256>>>(lengths, h0, out, bhh0, bih1, bhh1);
}